// round 1
// baseline (speedup 1.0000x reference)
#include <cuda_runtime.h>
#include <math.h>

// Problem constants (fixed shapes for this problem)
#define BB 16384   // batch
#define CC 2048    // prototypes
#define DD 128     // dim
#define BN 128     // samples per block (columns)
#define BCH 64     // centroids per chunk (rows)
#define PF 130     // padded pitch for transposed F tile (even -> float2-aligned)

// Scratch (static device arrays: allocation-free)
__device__ float g_S[2 * BB];            // per-sample sum of exp(logits) per side
__device__ float g_part[2 * (BB / 8)];   // per-block partial sums of (pos - lse)

// ---------------------------------------------------------------------------
// Kernel A: fused GEMM + exp + column-sum.
//   For side s, tile of 128 samples: S_b = sum_c exp( (M_c . f_b) / conc_c )
//   No max-subtraction needed: |logit| <= 2 (unit vectors, conc >= 0.5).
// ---------------------------------------------------------------------------
__global__ __launch_bounds__(256, 2)
void gemm_exp_sum_kernel(const float* __restrict__ features,
                         const float* __restrict__ features_I,
                         const float* __restrict__ M0,
                         const float* __restrict__ M1,
                         const float* __restrict__ conc0,
                         const float* __restrict__ conc1)
{
    extern __shared__ float sm[];
    float* Fs    = sm;                 // [DD][PF]  : Fs[k][col] (transposed)
    float* Ms    = sm + DD * PF;       // [BCH][DD] : row-major (broadcast reads)
    float* iconc = Ms + BCH * DD;      // [BCH]

    const int side = blockIdx.y;
    const float* __restrict__ F    = (side == 0) ? features_I : features;
    const float* __restrict__ M    = (side == 0) ? M0 : M1;
    const float* __restrict__ conc = (side == 0) ? conc0 : conc1;

    const int b0  = blockIdx.x * BN;
    const int tid = threadIdx.x;
    const int tx  = tid & 31;   // column group: cols tx*4 .. tx*4+3
    const int ty  = tid >> 5;   // row group:    rows ty*8 .. ty*8+7

    // Load F tile transposed: Fs[k][col] = F[b0+col][k]
    #pragma unroll
    for (int i = 0; i < 16; i++) {
        int idx = tid + i * 256;          // 0..4095 float4s
        int col = idx >> 5;               // sample within tile (0..127)
        int c4  = idx & 31;               // float4 index along D
        float4 v = reinterpret_cast<const float4*>(F + (size_t)(b0 + col) * DD)[c4];
        Fs[(4 * c4 + 0) * PF + col] = v.x;
        Fs[(4 * c4 + 1) * PF + col] = v.y;
        Fs[(4 * c4 + 2) * PF + col] = v.z;
        Fs[(4 * c4 + 3) * PF + col] = v.w;
    }

    float csum[4] = {0.f, 0.f, 0.f, 0.f};

    for (int ch = 0; ch < CC; ch += BCH) {
        __syncthreads();
        // Load M chunk row-major (coalesced, conflict-free)
        #pragma unroll
        for (int i = 0; i < 8; i++) {
            int idx = tid + i * 256;      // 0..2047 float4s
            int r  = idx >> 5;            // centroid row within chunk
            int c4 = idx & 31;
            reinterpret_cast<float4*>(Ms + r * DD)[c4] =
                reinterpret_cast<const float4*>(M + (size_t)(ch + r) * DD)[c4];
        }
        if (tid < BCH) iconc[tid] = 1.0f / conc[ch + tid];
        __syncthreads();

        float acc[8][4];
        #pragma unroll
        for (int m = 0; m < 8; m++)
            #pragma unroll
            for (int j = 0; j < 4; j++) acc[m][j] = 0.f;

        #pragma unroll 4
        for (int k = 0; k < DD; k++) {
            // 4 column (sample) values for this thread
            float2 bv0 = *reinterpret_cast<const float2*>(&Fs[k * PF + tx * 4]);
            float2 bv1 = *reinterpret_cast<const float2*>(&Fs[k * PF + tx * 4 + 2]);
            float b0v = bv0.x, b1v = bv0.y, b2v = bv1.x, b3v = bv1.y;
            #pragma unroll
            for (int m = 0; m < 8; m++) {
                float a = Ms[(ty * 8 + m) * DD + k];   // broadcast within warp
                acc[m][0] = fmaf(a, b0v, acc[m][0]);
                acc[m][1] = fmaf(a, b1v, acc[m][1]);
                acc[m][2] = fmaf(a, b2v, acc[m][2]);
                acc[m][3] = fmaf(a, b3v, acc[m][3]);
            }
        }

        // Epilogue: exp(logit) accumulated into per-thread column sums
        #pragma unroll
        for (int m = 0; m < 8; m++) {
            float ic = iconc[ty * 8 + m];
            csum[0] += __expf(acc[m][0] * ic);
            csum[1] += __expf(acc[m][1] * ic);
            csum[2] += __expf(acc[m][2] * ic);
            csum[3] += __expf(acc[m][3] * ic);
        }
    }

    // Reduce column sums across the 8 row-groups (reuse Ms as red[8][128])
    __syncthreads();
    float* red = Ms;
    red[ty * 128 + tx * 4 + 0] = csum[0];
    red[ty * 128 + tx * 4 + 1] = csum[1];
    red[ty * 128 + tx * 4 + 2] = csum[2];
    red[ty * 128 + tx * 4 + 3] = csum[3];
    __syncthreads();
    if (tid < 128) {
        float s = 0.f;
        #pragma unroll
        for (int t = 0; t < 8; t++) s += red[t * 128 + tid];
        g_S[side * BB + b0 + tid] = s;
    }
}

// ---------------------------------------------------------------------------
// Kernel B: positive logit + per-block partial of sum(pos - log S).
// One warp per sample; 8 samples per block.
// ---------------------------------------------------------------------------
__global__ __launch_bounds__(256)
void pos_kernel(const float* __restrict__ features,
                const float* __restrict__ features_I,
                const float* __restrict__ M0,
                const float* __restrict__ M1,
                const float* __restrict__ conc0,
                const float* __restrict__ conc1,
                const int* __restrict__ lab0,
                const int* __restrict__ lab1)
{
    const int side = blockIdx.y;
    const float* __restrict__ F    = (side == 0) ? features_I : features;
    const float* __restrict__ M    = (side == 0) ? M0 : M1;
    const float* __restrict__ conc = (side == 0) ? conc0 : conc1;
    const int*   __restrict__ lab  = (side == 0) ? lab0 : lab1;

    const int w    = threadIdx.x >> 5;
    const int lane = threadIdx.x & 31;
    const int b    = blockIdx.x * 8 + w;

    int l = lab[b];
    float4 f = reinterpret_cast<const float4*>(F + (size_t)b * DD)[lane];
    float4 m = reinterpret_cast<const float4*>(M + (size_t)l * DD)[lane];
    float d = f.x * m.x + f.y * m.y + f.z * m.z + f.w * m.w;
    #pragma unroll
    for (int o = 16; o > 0; o >>= 1) d += __shfl_xor_sync(0xFFFFFFFFu, d, o);

    __shared__ float ws[8];
    if (lane == 0) ws[w] = d / conc[l] - logf(g_S[side * BB + b]);
    __syncthreads();
    if (threadIdx.x == 0) {
        float s = 0.f;
        #pragma unroll
        for (int i = 0; i < 8; i++) s += ws[i];
        g_part[side * (BB / 8) + blockIdx.x] = s;
    }
}

// ---------------------------------------------------------------------------
// Kernel C: deterministic final reduction + scaling.
// ---------------------------------------------------------------------------
__global__ __launch_bounds__(256)
void finish_kernel(const int* __restrict__ lbp, float* __restrict__ out)
{
    __shared__ float smr[256];
    float s = 0.f;
    for (int i = threadIdx.x; i < 2 * (BB / 8); i += 256) s += g_part[i];
    smr[threadIdx.x] = s;
    __syncthreads();
    for (int st = 128; st > 0; st >>= 1) {
        if (threadIdx.x < st) smr[threadIdx.x] += smr[threadIdx.x + st];
        __syncthreads();
    }
    if (threadIdx.x == 0) {
        // lb is a scalar; tolerate either int32 or float32 encoding.
        int iv = lbp[0];
        float lbv = (iv > 1000000 || iv < -1000000) ? __int_as_float(iv) : (float)iv;
        out[0] = (-lbv) * 0.5f / (float)BB * smr[0];
    }
}

// ---------------------------------------------------------------------------
// Launch
// ---------------------------------------------------------------------------
extern "C" void kernel_launch(void* const* d_in, const int* in_sizes, int n_in,
                              void* d_out, int out_size)
{
    const float* features       = (const float*)d_in[0];
    const float* features_I     = (const float*)d_in[1];
    const float* M_kmeans       = (const float*)d_in[2];
    const float* M_kmeans_I     = (const float*)d_in[3];
    const float* concentrations = (const float*)d_in[4];
    const float* concentr_I     = (const float*)d_in[5];
    const int*   labels         = (const int*)d_in[6];
    const int*   labels_I       = (const int*)d_in[7];
    const int*   lb             = (n_in > 8) ? (const int*)d_in[8] : nullptr;
    float* out = (float*)d_out;

    const int smem_bytes = (DD * PF + BCH * DD + BCH) * (int)sizeof(float);
    cudaFuncSetAttribute(gemm_exp_sum_kernel,
                         cudaFuncAttributeMaxDynamicSharedMemorySize, smem_bytes);

    dim3 gridA(BB / BN, 2);
    gemm_exp_sum_kernel<<<gridA, 256, smem_bytes>>>(
        features, features_I, M_kmeans, M_kmeans_I, concentrations, concentr_I);

    dim3 gridB(BB / 8, 2);
    pos_kernel<<<gridB, 256>>>(
        features, features_I, M_kmeans, M_kmeans_I, concentrations, concentr_I,
        labels, labels_I);

    finish_kernel<<<1, 256>>>(lb, out);
}

// round 3
// speedup vs baseline: 5.3020x; 5.3020x over previous
#include <cuda_runtime.h>
#include <cuda_bf16.h>
#include <math.h>
#include <stdint.h>

#define BB 16384
#define CC 2048
#define DDIM 128
#define TILE_B 128          // samples per CTA
#define TILE_C 64           // centroids per chunk
#define NCH (CC / TILE_C)   // 32 chunks
#define ROWB 256            // bytes per smem row (128 bf16)

// ---------------- scratch ----------------
__device__ __align__(16) __nv_bfloat16 g_Mb[2 * CC * DDIM]; // bf16 M, row-major
__device__ float g_S[2 * BB];
__device__ float g_part[2 * (BB / 8)];

// ---------------- smem layout (bytes) ----------------
#define SM_F   0
#define SM_M0  32768
#define SM_M1  49152
#define SM_IC  65536
#define SM_RED 73728
#define SM_TOT 74240

__device__ __forceinline__ uint32_t smem_u32(const void* p) {
    uint32_t a;
    asm("{ .reg .u64 t; cvta.to.shared.u64 t, %1; cvt.u32.u64 %0, t; }" : "=r"(a) : "l"(p));
    return a;
}
__device__ __forceinline__ float ex2f(float x) {
    float y; asm("ex2.approx.f32 %0, %1;" : "=f"(y) : "f"(x)); return y;
}
__device__ __forceinline__ void ldsm_x4(uint32_t& r0, uint32_t& r1, uint32_t& r2,
                                        uint32_t& r3, uint32_t addr) {
    asm volatile("ldmatrix.sync.aligned.m8n8.x4.shared.b16 {%0,%1,%2,%3}, [%4];"
                 : "=r"(r0), "=r"(r1), "=r"(r2), "=r"(r3) : "r"(addr));
}
__device__ __forceinline__ void mma_bf16(float& c0, float& c1, float& c2, float& c3,
                                         uint32_t a0, uint32_t a1, uint32_t a2, uint32_t a3,
                                         uint32_t b0, uint32_t b1) {
    asm volatile("mma.sync.aligned.m16n8k16.row.col.f32.bf16.bf16.f32 "
                 "{%0,%1,%2,%3}, {%4,%5,%6,%7}, {%8,%9}, {%0,%1,%2,%3};"
                 : "+f"(c0), "+f"(c1), "+f"(c2), "+f"(c3)
                 : "r"(a0), "r"(a1), "r"(a2), "r"(a3), "r"(b0), "r"(b1));
}
#define CP_ASYNC16(dst, src) \
    asm volatile("cp.async.cg.shared.global [%0], [%1], 16;" :: "r"(dst), "l"(src) : "memory")
#define CP_COMMIT() asm volatile("cp.async.commit_group;" ::: "memory")
#define CP_WAIT1()  asm volatile("cp.async.wait_group 1;" ::: "memory")
#define CP_WAIT0()  asm volatile("cp.async.wait_group 0;" ::: "memory")

// ---------------- prep: M fp32 -> bf16 row-major ----------------
__global__ __launch_bounds__(256)
void convM_kernel(const float* __restrict__ M0, const float* __restrict__ M1)
{
    int i = (blockIdx.x * 256 + threadIdx.x) * 4;     // float4 granularity
    const int n = CC * DDIM;
    const float* src = (i < n) ? M0 : M1;
    int off = (i < n) ? i : i - n;
    float4 v = *reinterpret_cast<const float4*>(src + off);
    __nv_bfloat16 b[4] = { __float2bfloat16_rn(v.x), __float2bfloat16_rn(v.y),
                           __float2bfloat16_rn(v.z), __float2bfloat16_rn(v.w) };
    *reinterpret_cast<uint2*>(g_Mb + i) = *reinterpret_cast<uint2*>(b);
}

// ---------------- main fused GEMM + exp + row-sum ----------------
__global__ __launch_bounds__(256, 2)
void main_kernel(const float* __restrict__ features,
                 const float* __restrict__ features_I,
                 const float* __restrict__ conc0,
                 const float* __restrict__ conc1)
{
    extern __shared__ __align__(1024) unsigned char smem[];
    const uint32_t sb = smem_u32(smem);
    const int tid  = threadIdx.x;
    const int wid  = tid >> 5;
    const int lane = tid & 31;
    const int wr   = wid >> 2;        // 0..1 : m-offset wr*64
    const int wc   = wid & 3;         // 0..3 : n-offset wc*16
    const int side = blockIdx.y;
    const int bx   = blockIdx.x;

    const float* __restrict__ F    = side ? features : features_I;
    const float* __restrict__ conc = side ? conc1 : conc0;
    const __nv_bfloat16* __restrict__ Msrc = g_Mb + (size_t)side * CC * DDIM;

    float* __restrict__ ic  = reinterpret_cast<float*>(smem + SM_IC);
    float* __restrict__ red = reinterpret_cast<float*>(smem + SM_RED);

    // ic = log2(e) / conc ; zero reduction buffer
    #pragma unroll
    for (int i = tid; i < CC; i += 256) ic[i] = 1.4426950408889634f / conc[i];
    if (tid < TILE_B) red[tid] = 0.f;

    // F tile: fp32 -> bf16 into swizzled smem (row*256B, unit^(row&7))
    {
        const float* Fp = F + (size_t)bx * TILE_B * DDIM;
        #pragma unroll
        for (int j = 0; j < 8; j++) {
            int u   = tid + j * 256;            // 0..2047 16B units
            int row = u >> 4, un = u & 15;
            const float4* p = reinterpret_cast<const float4*>(Fp + row * DDIM + un * 8);
            float4 a = p[0], b = p[1];
            __nv_bfloat16 t[8] = {
                __float2bfloat16_rn(a.x), __float2bfloat16_rn(a.y),
                __float2bfloat16_rn(a.z), __float2bfloat16_rn(a.w),
                __float2bfloat16_rn(b.x), __float2bfloat16_rn(b.y),
                __float2bfloat16_rn(b.z), __float2bfloat16_rn(b.w) };
            *reinterpret_cast<uint4*>(smem + SM_F + row * ROWB + ((un ^ (row & 7)) << 4)) =
                *reinterpret_cast<uint4*>(t);
        }
    }

    // prefetch chunk 0
    {
        const __nv_bfloat16* Mc = Msrc;
        #pragma unroll
        for (int j = 0; j < 4; j++) {
            int u = tid + j * 256;              // 64 rows x 16 units
            int row = u >> 4, un = u & 15;
            CP_ASYNC16(sb + SM_M0 + row * ROWB + ((un ^ (row & 7)) << 4),
                       Mc + row * DDIM + un * 8);
        }
        CP_COMMIT();
    }

    // per-thread ldmatrix geometry
    const int j8 = lane & 7, g = lane >> 3;
    const int arow = wr * 64 + ((g & 1) << 3) + j8;     // + mt*16
    const int ap   = g >> 1;                             // unit parity
    const int brow = ((g >> 1) << 3) + j8;               // within chunk + wc*16
    const int bp   = g & 1;
    const uint32_t a_base = sb + SM_F + arow * ROWB;
    const int a_swz = arow & 7;
    const int b_row_full = wc * 16 + brow;
    const uint32_t b_off = b_row_full * ROWB;
    const int b_swz = b_row_full & 7;

    float rsum[8];
    #pragma unroll
    for (int i = 0; i < 8; i++) rsum[i] = 0.f;

    for (int i = 0; i < NCH; i++) {
        const int s = i & 1;
        if (i + 1 < NCH) {
            const __nv_bfloat16* Mc = Msrc + (size_t)(i + 1) * TILE_C * DDIM;
            const uint32_t dst = sb + (s ? SM_M0 : SM_M1);
            #pragma unroll
            for (int j = 0; j < 4; j++) {
                int u = tid + j * 256;
                int row = u >> 4, un = u & 15;
                CP_ASYNC16(dst + row * ROWB + ((un ^ (row & 7)) << 4),
                           Mc + row * DDIM + un * 8);
            }
            CP_COMMIT();
            CP_WAIT1();
        } else {
            CP_WAIT0();
        }
        __syncthreads();

        const uint32_t mb = sb + (s ? SM_M1 : SM_M0) + b_off;

        float c[4][2][4];
        #pragma unroll
        for (int mt = 0; mt < 4; mt++)
            #pragma unroll
            for (int nt = 0; nt < 2; nt++)
                #pragma unroll
                for (int q = 0; q < 4; q++) c[mt][nt][q] = 0.f;

        #pragma unroll
        for (int ks = 0; ks < 8; ks++) {
            uint32_t a[4][4], b[4];
            const uint32_t ua = ((ks * 2 + ap) ^ a_swz) << 4;
            #pragma unroll
            for (int mt = 0; mt < 4; mt++)
                ldsm_x4(a[mt][0], a[mt][1], a[mt][2], a[mt][3],
                        a_base + mt * 16 * ROWB + ua);
            ldsm_x4(b[0], b[1], b[2], b[3], mb + (((ks * 2 + bp) ^ b_swz) << 4));
            #pragma unroll
            for (int mt = 0; mt < 4; mt++) {
                mma_bf16(c[mt][0][0], c[mt][0][1], c[mt][0][2], c[mt][0][3],
                         a[mt][0], a[mt][1], a[mt][2], a[mt][3], b[0], b[1]);
                mma_bf16(c[mt][1][0], c[mt][1][1], c[mt][1][2], c[mt][1][3],
                         a[mt][0], a[mt][1], a[mt][2], a[mt][3], b[2], b[3]);
            }
        }
        __syncthreads();   // stage fully read; next prefetch may overwrite

        // epilogue: exp2(d * ic) accumulated into per-thread row sums
        const int colb = i * TILE_C + wc * 16 + ((lane & 3) << 1);
        const float2 ic0 = *reinterpret_cast<const float2*>(ic + colb);
        const float2 ic1 = *reinterpret_cast<const float2*>(ic + colb + 8);
        #pragma unroll
        for (int mt = 0; mt < 4; mt++) {
            rsum[mt * 2 + 0] += ex2f(c[mt][0][0] * ic0.x) + ex2f(c[mt][0][1] * ic0.y)
                              + ex2f(c[mt][1][0] * ic1.x) + ex2f(c[mt][1][1] * ic1.y);
            rsum[mt * 2 + 1] += ex2f(c[mt][0][2] * ic0.x) + ex2f(c[mt][0][3] * ic0.y)
                              + ex2f(c[mt][1][2] * ic1.x) + ex2f(c[mt][1][3] * ic1.y);
        }
    }

    // reduce within quad (lanes differing in lane&3), then across warp-cols via smem atomics
    #pragma unroll
    for (int i = 0; i < 8; i++) {
        rsum[i] += __shfl_xor_sync(0xFFFFFFFFu, rsum[i], 1);
        rsum[i] += __shfl_xor_sync(0xFFFFFFFFu, rsum[i], 2);
    }
    if ((lane & 3) == 0) {
        const int r0 = wr * 64 + (lane >> 2);
        #pragma unroll
        for (int mt = 0; mt < 4; mt++) {
            atomicAdd(red + r0 + mt * 16, rsum[mt * 2 + 0]);
            atomicAdd(red + r0 + mt * 16 + 8, rsum[mt * 2 + 1]);
        }
    }
    __syncthreads();
    if (tid < TILE_B)
        g_S[side * BB + bx * TILE_B + tid] = red[tid];
}

// ---------------- positive logit + partials (exact fp32) ----------------
__global__ __launch_bounds__(256)
void pos_kernel(const float* __restrict__ features,
                const float* __restrict__ features_I,
                const float* __restrict__ M0,
                const float* __restrict__ M1,
                const float* __restrict__ conc0,
                const float* __restrict__ conc1,
                const int* __restrict__ lab0,
                const int* __restrict__ lab1)
{
    const int side = blockIdx.y;
    const float* __restrict__ F    = (side == 0) ? features_I : features;
    const float* __restrict__ M    = (side == 0) ? M0 : M1;
    const float* __restrict__ conc = (side == 0) ? conc0 : conc1;
    const int*   __restrict__ lab  = (side == 0) ? lab0 : lab1;

    const int w = threadIdx.x >> 5, lane = threadIdx.x & 31;
    const int b = blockIdx.x * 8 + w;

    int l = lab[b];
    float4 f = reinterpret_cast<const float4*>(F + (size_t)b * DDIM)[lane];
    float4 m = reinterpret_cast<const float4*>(M + (size_t)l * DDIM)[lane];
    float d = f.x * m.x + f.y * m.y + f.z * m.z + f.w * m.w;
    #pragma unroll
    for (int o = 16; o > 0; o >>= 1) d += __shfl_xor_sync(0xFFFFFFFFu, d, o);

    __shared__ float ws[8];
    if (lane == 0) ws[w] = d / conc[l] - logf(g_S[side * BB + b]);
    __syncthreads();
    if (threadIdx.x == 0) {
        float s = 0.f;
        #pragma unroll
        for (int i = 0; i < 8; i++) s += ws[i];
        g_part[side * (BB / 8) + blockIdx.x] = s;
    }
}

__global__ __launch_bounds__(256)
void finish_kernel(const int* __restrict__ lbp, float* __restrict__ out)
{
    __shared__ float smr[256];
    float s = 0.f;
    for (int i = threadIdx.x; i < 2 * (BB / 8); i += 256) s += g_part[i];
    smr[threadIdx.x] = s;
    __syncthreads();
    for (int st = 128; st > 0; st >>= 1) {
        if (threadIdx.x < st) smr[threadIdx.x] += smr[threadIdx.x + st];
        __syncthreads();
    }
    if (threadIdx.x == 0) {
        int iv = lbp[0];
        float lbv = (iv > 1000000 || iv < -1000000) ? __int_as_float(iv) : (float)iv;
        out[0] = (-lbv) * 0.5f / (float)BB * smr[0];
    }
}

// ---------------- launch ----------------
extern "C" void kernel_launch(void* const* d_in, const int* in_sizes, int n_in,
                              void* d_out, int out_size)
{
    const float* features       = (const float*)d_in[0];
    const float* features_I     = (const float*)d_in[1];
    const float* M_kmeans       = (const float*)d_in[2];
    const float* M_kmeans_I     = (const float*)d_in[3];
    const float* concentrations = (const float*)d_in[4];
    const float* concentr_I     = (const float*)d_in[5];
    const int*   labels         = (const int*)d_in[6];
    const int*   labels_I       = (const int*)d_in[7];
    const int*   lb             = (n_in > 8) ? (const int*)d_in[8] : nullptr;
    float* out = (float*)d_out;

    // g_Mb[0] pairs with features_I (side 0 uses M_kmeans), g_Mb[1] with features
    convM_kernel<<<(2 * CC * DDIM / 4) / 256, 256>>>(M_kmeans, M_kmeans_I);

    cudaFuncSetAttribute(main_kernel,
                         cudaFuncAttributeMaxDynamicSharedMemorySize, SM_TOT);
    main_kernel<<<dim3(BB / TILE_B, 2), 256, SM_TOT>>>(
        features, features_I, concentrations, concentr_I);

    pos_kernel<<<dim3(BB / 8, 2), 256>>>(features, features_I, M_kmeans, M_kmeans_I,
                                         concentrations, concentr_I, labels, labels_I);
    finish_kernel<<<1, 256>>>(lb, out);
}

// round 5
// speedup vs baseline: 5.8411x; 1.1017x over previous
#include <cuda_runtime.h>
#include <cuda_bf16.h>
#include <math.h>
#include <stdint.h>

#define BB 16384
#define CC 2048
#define DDIM 128
#define TILE_B 128          // samples per CTA
#define TILE_C 64           // centroids per chunk
#define NCH (CC / TILE_C)   // 32 chunks
#define ROWB 256            // bytes per smem row (128 bf16)
#define LN2F 0.6931471805599453f

// ---------------- scratch ----------------
__device__ __align__(16) __nv_bfloat16 g_Mb[2 * CC * DDIM]; // bf16 M, row-major
__device__ float g_part[2 * (BB / TILE_B)];                 // 256 per-CTA partials

// ---------------- smem layout (bytes) ----------------
#define SM_F   0
#define SM_M0  32768
#define SM_M1  49152
#define SM_IC  65536
#define SM_RED 73728
#define SM_WS  74240
#define SM_TOT 74304

__device__ __forceinline__ uint32_t smem_u32(const void* p) {
    uint32_t a;
    asm("{ .reg .u64 t; cvta.to.shared.u64 t, %1; cvt.u32.u64 %0, t; }" : "=r"(a) : "l"(p));
    return a;
}
__device__ __forceinline__ float ex2f(float x) {
    float y; asm("ex2.approx.f32 %0, %1;" : "=f"(y) : "f"(x)); return y;
}
__device__ __forceinline__ void ldsm_x4(uint32_t& r0, uint32_t& r1, uint32_t& r2,
                                        uint32_t& r3, uint32_t addr) {
    asm volatile("ldmatrix.sync.aligned.m8n8.x4.shared.b16 {%0,%1,%2,%3}, [%4];"
                 : "=r"(r0), "=r"(r1), "=r"(r2), "=r"(r3) : "r"(addr));
}
__device__ __forceinline__ void mma_bf16(float& c0, float& c1, float& c2, float& c3,
                                         uint32_t a0, uint32_t a1, uint32_t a2, uint32_t a3,
                                         uint32_t b0, uint32_t b1) {
    asm volatile("mma.sync.aligned.m16n8k16.row.col.f32.bf16.bf16.f32 "
                 "{%0,%1,%2,%3}, {%4,%5,%6,%7}, {%8,%9}, {%0,%1,%2,%3};"
                 : "+f"(c0), "+f"(c1), "+f"(c2), "+f"(c3)
                 : "r"(a0), "r"(a1), "r"(a2), "r"(a3), "r"(b0), "r"(b1));
}
#define CP_ASYNC16(dst, src) \
    asm volatile("cp.async.cg.shared.global [%0], [%1], 16;" :: "r"(dst), "l"(src) : "memory")
#define CP_COMMIT() asm volatile("cp.async.commit_group;" ::: "memory")
#define CP_WAIT1()  asm volatile("cp.async.wait_group 1;" ::: "memory")
#define CP_WAIT0()  asm volatile("cp.async.wait_group 0;" ::: "memory")

// ---------------- prep: M fp32 -> bf16 row-major ----------------
__global__ __launch_bounds__(256)
void convM_kernel(const float* __restrict__ M0, const float* __restrict__ M1)
{
    int i = (blockIdx.x * 256 + threadIdx.x) * 4;
    const int n = CC * DDIM;
    const float* src = (i < n) ? M0 : M1;
    int off = (i < n) ? i : i - n;
    float4 v = *reinterpret_cast<const float4*>(src + off);
    __nv_bfloat16 b[4] = { __float2bfloat16_rn(v.x), __float2bfloat16_rn(v.y),
                           __float2bfloat16_rn(v.z), __float2bfloat16_rn(v.w) };
    *reinterpret_cast<uint2*>(g_Mb + i) = *reinterpret_cast<uint2*>(b);
}

// ---------------- main fused GEMM + exp + row-sum + positive + partial ----------------
__global__ __launch_bounds__(256, 2)
void main_kernel(const float* __restrict__ features,
                 const float* __restrict__ features_I,
                 const float* __restrict__ M0,
                 const float* __restrict__ M1,
                 const float* __restrict__ conc0,
                 const float* __restrict__ conc1,
                 const int* __restrict__ lab0,
                 const int* __restrict__ lab1)
{
    extern __shared__ __align__(1024) unsigned char smem[];
    const uint32_t sb = smem_u32(smem);
    const int tid  = threadIdx.x;
    const int wid  = tid >> 5;
    const int lane = tid & 31;
    const int wr   = wid >> 2;        // 0..1 : m-offset wr*64
    const int wc   = wid & 3;         // 0..3 : n-offset wc*16
    const int side = blockIdx.y;
    const int bx   = blockIdx.x;

    const float* __restrict__ F    = side ? features : features_I;
    const float* __restrict__ Mf   = side ? M1 : M0;
    const float* __restrict__ conc = side ? conc1 : conc0;
    const int*   __restrict__ lab  = side ? lab1 : lab0;
    const __nv_bfloat16* __restrict__ Msrc = g_Mb + (size_t)side * CC * DDIM;

    float* __restrict__ ic  = reinterpret_cast<float*>(smem + SM_IC);
    float* __restrict__ red = reinterpret_cast<float*>(smem + SM_RED);
    float* __restrict__ ws  = reinterpret_cast<float*>(smem + SM_WS);

    // ic = log2(e) / conc ; zero reduction buffer
    #pragma unroll
    for (int i = tid; i < CC; i += 256) ic[i] = 1.4426950408889634f / conc[i];
    if (tid < TILE_B) red[tid] = 0.f;

    // F tile: fp32 -> bf16 into swizzled smem (row*256B, unit^(row&7))
    {
        const float* Fp = F + (size_t)bx * TILE_B * DDIM;
        #pragma unroll
        for (int j = 0; j < 8; j++) {
            int u   = tid + j * 256;            // 0..2047 16B units
            int row = u >> 4, un = u & 15;
            const float4* p = reinterpret_cast<const float4*>(Fp + row * DDIM + un * 8);
            float4 a = p[0], b = p[1];
            __nv_bfloat16 t[8] = {
                __float2bfloat16_rn(a.x), __float2bfloat16_rn(a.y),
                __float2bfloat16_rn(a.z), __float2bfloat16_rn(a.w),
                __float2bfloat16_rn(b.x), __float2bfloat16_rn(b.y),
                __float2bfloat16_rn(b.z), __float2bfloat16_rn(b.w) };
            *reinterpret_cast<uint4*>(smem + SM_F + row * ROWB + ((un ^ (row & 7)) << 4)) =
                *reinterpret_cast<uint4*>(t);
        }
    }

    // prefetch chunk 0
    {
        const __nv_bfloat16* Mc = Msrc;
        #pragma unroll
        for (int j = 0; j < 4; j++) {
            int u = tid + j * 256;              // 64 rows x 16 units
            int row = u >> 4, un = u & 15;
            CP_ASYNC16(sb + SM_M0 + row * ROWB + ((un ^ (row & 7)) << 4),
                       Mc + row * DDIM + un * 8);
        }
        CP_COMMIT();
    }

    // per-thread ldmatrix geometry
    const int j8 = lane & 7, g = lane >> 3;
    const int arow = wr * 64 + ((g & 1) << 3) + j8;     // + mt*16
    const int ap   = g >> 1;
    const int brow = ((g >> 1) << 3) + j8;
    const int bp   = g & 1;
    const uint32_t a_base = sb + SM_F + arow * ROWB;
    const int a_swz = arow & 7;
    const int b_row_full = wc * 16 + brow;
    const uint32_t b_off = b_row_full * ROWB;
    const int b_swz = b_row_full & 7;

    float rsum[8];
    #pragma unroll
    for (int i = 0; i < 8; i++) rsum[i] = 0.f;

    for (int i = 0; i < NCH; i++) {
        const int s = i & 1;
        if (i + 1 < NCH) {
            const __nv_bfloat16* Mc = Msrc + (size_t)(i + 1) * TILE_C * DDIM;
            const uint32_t dst = sb + (s ? SM_M0 : SM_M1);
            #pragma unroll
            for (int j = 0; j < 4; j++) {
                int u = tid + j * 256;
                int row = u >> 4, un = u & 15;
                CP_ASYNC16(dst + row * ROWB + ((un ^ (row & 7)) << 4),
                           Mc + row * DDIM + un * 8);
            }
            CP_COMMIT();
            CP_WAIT1();
        } else {
            CP_WAIT0();
        }
        __syncthreads();

        const uint32_t mb = sb + (s ? SM_M1 : SM_M0) + b_off;

        float c[4][2][4];
        #pragma unroll
        for (int mt = 0; mt < 4; mt++)
            #pragma unroll
            for (int nt = 0; nt < 2; nt++)
                #pragma unroll
                for (int q = 0; q < 4; q++) c[mt][nt][q] = 0.f;

        #pragma unroll
        for (int ks = 0; ks < 8; ks++) {
            uint32_t a[4][4], b[4];
            const uint32_t ua = ((ks * 2 + ap) ^ a_swz) << 4;
            #pragma unroll
            for (int mt = 0; mt < 4; mt++)
                ldsm_x4(a[mt][0], a[mt][1], a[mt][2], a[mt][3],
                        a_base + mt * 16 * ROWB + ua);
            ldsm_x4(b[0], b[1], b[2], b[3], mb + (((ks * 2 + bp) ^ b_swz) << 4));
            #pragma unroll
            for (int mt = 0; mt < 4; mt++) {
                mma_bf16(c[mt][0][0], c[mt][0][1], c[mt][0][2], c[mt][0][3],
                         a[mt][0], a[mt][1], a[mt][2], a[mt][3], b[0], b[1]);
                mma_bf16(c[mt][1][0], c[mt][1][1], c[mt][1][2], c[mt][1][3],
                         a[mt][0], a[mt][1], a[mt][2], a[mt][3], b[2], b[3]);
            }
        }
        __syncthreads();   // stage fully read; next prefetch may overwrite

        const int colb = i * TILE_C + wc * 16 + ((lane & 3) << 1);
        const float2 ic0 = *reinterpret_cast<const float2*>(ic + colb);
        const float2 ic1 = *reinterpret_cast<const float2*>(ic + colb + 8);
        #pragma unroll
        for (int mt = 0; mt < 4; mt++) {
            rsum[mt * 2 + 0] += ex2f(c[mt][0][0] * ic0.x) + ex2f(c[mt][0][1] * ic0.y)
                              + ex2f(c[mt][1][0] * ic1.x) + ex2f(c[mt][1][1] * ic1.y);
            rsum[mt * 2 + 1] += ex2f(c[mt][0][2] * ic0.x) + ex2f(c[mt][0][3] * ic0.y)
                              + ex2f(c[mt][1][2] * ic1.x) + ex2f(c[mt][1][3] * ic1.y);
        }
    }

    // reduce row sums: quad shfl, then cross-warp smem atomics
    #pragma unroll
    for (int i = 0; i < 8; i++) {
        rsum[i] += __shfl_xor_sync(0xFFFFFFFFu, rsum[i], 1);
        rsum[i] += __shfl_xor_sync(0xFFFFFFFFu, rsum[i], 2);
    }
    if ((lane & 3) == 0) {
        const int r0 = wr * 64 + (lane >> 2);
        #pragma unroll
        for (int mt = 0; mt < 4; mt++) {
            atomicAdd(red + r0 + mt * 16, rsum[mt * 2 + 0]);
            atomicAdd(red + r0 + mt * 16 + 8, rsum[mt * 2 + 1]);
        }
    }
    __syncthreads();       // red[] = S per sample, complete

    // ---- fused positive logit + per-CTA partial (exact fp32) ----
    // warp w handles samples w*16 .. w*16+15
    float psum = 0.f;
    const int b0 = bx * TILE_B;
    #pragma unroll 4
    for (int j = 0; j < 16; j++) {
        const int bl = wid * 16 + j;             // sample within tile
        const int bgl = b0 + bl;                 // global sample
        const int l = lab[bgl];
        float4 f = reinterpret_cast<const float4*>(F + (size_t)bgl * DDIM)[lane];
        float4 m = reinterpret_cast<const float4*>(Mf + (size_t)l * DDIM)[lane];
        float d = f.x * m.x + f.y * m.y + f.z * m.z + f.w * m.w;
        #pragma unroll
        for (int o = 16; o > 0; o >>= 1) d += __shfl_xor_sync(0xFFFFFFFFu, d, o);
        if (lane == 0)
            psum += d * ic[l] * LN2F - logf(red[bl]);   // pos/conc - ln S
    }
    if (lane == 0) ws[wid] = psum;
    __syncthreads();
    if (tid == 0) {
        float s = 0.f;
        #pragma unroll
        for (int i = 0; i < 8; i++) s += ws[i];
        g_part[side * (BB / TILE_B) + bx] = s;
    }
}

// ---------------- final reduction ----------------
__global__ __launch_bounds__(256)
void finish_kernel(const int* __restrict__ lbp, float* __restrict__ out)
{
    __shared__ float smr[256];
    smr[threadIdx.x] = g_part[threadIdx.x];     // exactly 256 partials
    __syncthreads();
    for (int st = 128; st > 0; st >>= 1) {
        if (threadIdx.x < st) smr[threadIdx.x] += smr[threadIdx.x + st];
        __syncthreads();
    }
    if (threadIdx.x == 0) {
        int iv = lbp[0];
        float lbv = (iv > 1000000 || iv < -1000000) ? __int_as_float(iv) : (float)iv;
        out[0] = (-lbv) * 0.5f / (float)BB * smr[0];
    }
}

// ---------------- launch ----------------
extern "C" void kernel_launch(void* const* d_in, const int* in_sizes, int n_in,
                              void* d_out, int out_size)
{
    const float* features       = (const float*)d_in[0];
    const float* features_I     = (const float*)d_in[1];
    const float* M_kmeans       = (const float*)d_in[2];
    const float* M_kmeans_I     = (const float*)d_in[3];
    const float* concentrations = (const float*)d_in[4];
    const float* concentr_I     = (const float*)d_in[5];
    const int*   labels         = (const int*)d_in[6];
    const int*   labels_I       = (const int*)d_in[7];
    const int*   lb             = (n_in > 8) ? (const int*)d_in[8] : nullptr;
    float* out = (float*)d_out;

    convM_kernel<<<(2 * CC * DDIM / 4) / 256, 256>>>(M_kmeans, M_kmeans_I);

    cudaFuncSetAttribute(main_kernel,
                         cudaFuncAttributeMaxDynamicSharedMemorySize, SM_TOT);
    main_kernel<<<dim3(BB / TILE_B, 2), 256, SM_TOT>>>(
        features, features_I, M_kmeans, M_kmeans_I,
        concentrations, concentr_I, labels, labels_I);

    finish_kernel<<<1, 256>>>(lb, out);
}

// round 6
// speedup vs baseline: 6.3302x; 1.0837x over previous
#include <cuda_runtime.h>
#include <cuda_bf16.h>
#include <math.h>
#include <stdint.h>

#define BB 16384
#define CC 2048
#define DDIM 128
#define TILE_B 128          // samples per CTA
#define TILE_C 64           // centroids per chunk
#define NCH (CC / TILE_C)   // 32 chunks
#define ROWB 256            // bytes per smem row (128 bf16)
#define LN2F 0.6931471805599453f
#define NBLK (2 * (BB / TILE_B))   // 256 CTAs total

// ---------------- scratch ----------------
__device__ __align__(16) __nv_bfloat16 g_Mb[2 * CC * DDIM]; // bf16 M, row-major
__device__ float g_part[NBLK];                              // per-CTA partials
__device__ unsigned int g_cnt;                              // completion counter

// ---------------- smem layout (bytes) ----------------
#define SM_F    0
#define SM_M0   32768
#define SM_M1   49152
#define SM_IC   65536
#define SM_RED  73728
#define SM_WS   74240
#define SM_FLAG 74272
#define SM_TOT  74304

__device__ __forceinline__ uint32_t smem_u32(const void* p) {
    uint32_t a;
    asm("{ .reg .u64 t; cvta.to.shared.u64 t, %1; cvt.u32.u64 %0, t; }" : "=r"(a) : "l"(p));
    return a;
}
__device__ __forceinline__ float ex2f(float x) {
    float y; asm("ex2.approx.f32 %0, %1;" : "=f"(y) : "f"(x)); return y;
}
__device__ __forceinline__ void ldsm_x4(uint32_t& r0, uint32_t& r1, uint32_t& r2,
                                        uint32_t& r3, uint32_t addr) {
    asm volatile("ldmatrix.sync.aligned.m8n8.x4.shared.b16 {%0,%1,%2,%3}, [%4];"
                 : "=r"(r0), "=r"(r1), "=r"(r2), "=r"(r3) : "r"(addr));
}
__device__ __forceinline__ void mma_bf16(float& c0, float& c1, float& c2, float& c3,
                                         uint32_t a0, uint32_t a1, uint32_t a2, uint32_t a3,
                                         uint32_t b0, uint32_t b1) {
    asm volatile("mma.sync.aligned.m16n8k16.row.col.f32.bf16.bf16.f32 "
                 "{%0,%1,%2,%3}, {%4,%5,%6,%7}, {%8,%9}, {%0,%1,%2,%3};"
                 : "+f"(c0), "+f"(c1), "+f"(c2), "+f"(c3)
                 : "r"(a0), "r"(a1), "r"(a2), "r"(a3), "r"(b0), "r"(b1));
}
#define CP_ASYNC16(dst, src) \
    asm volatile("cp.async.cg.shared.global [%0], [%1], 16;" :: "r"(dst), "l"(src) : "memory")
#define CP_COMMIT() asm volatile("cp.async.commit_group;" ::: "memory")
#define CP_WAIT1()  asm volatile("cp.async.wait_group 1;" ::: "memory")
#define CP_WAIT0()  asm volatile("cp.async.wait_group 0;" ::: "memory")

// ---------------- prep: M fp32 -> bf16 row-major ----------------
__global__ __launch_bounds__(256)
void convM_kernel(const float* __restrict__ M0, const float* __restrict__ M1)
{
    int i = (blockIdx.x * 256 + threadIdx.x) * 4;
    const int n = CC * DDIM;
    const float* src = (i < n) ? M0 : M1;
    int off = (i < n) ? i : i - n;
    float4 v = *reinterpret_cast<const float4*>(src + off);
    __nv_bfloat16 b[4] = { __float2bfloat16_rn(v.x), __float2bfloat16_rn(v.y),
                           __float2bfloat16_rn(v.z), __float2bfloat16_rn(v.w) };
    *reinterpret_cast<uint2*>(g_Mb + i) = *reinterpret_cast<uint2*>(b);
}

// ---------------- main: GEMM + exp + row-sum + positive + full reduction ----------------
__global__ __launch_bounds__(256, 2)
void main_kernel(const float* __restrict__ features,
                 const float* __restrict__ features_I,
                 const float* __restrict__ M0,
                 const float* __restrict__ M1,
                 const float* __restrict__ conc0,
                 const float* __restrict__ conc1,
                 const int* __restrict__ lab0,
                 const int* __restrict__ lab1,
                 const int* __restrict__ lbp,
                 float* __restrict__ out)
{
    extern __shared__ __align__(1024) unsigned char smem[];
    const uint32_t sb = smem_u32(smem);
    const int tid  = threadIdx.x;
    const int wid  = tid >> 5;
    const int lane = tid & 31;
    const int wm   = wid >> 1;        // 0..3 : m-offset wm*32
    const int wn   = wid & 1;         // 0..1 : n-offset wn*32
    const int side = blockIdx.y;
    const int bx   = blockIdx.x;

    const float* __restrict__ F    = side ? features : features_I;
    const float* __restrict__ Mf   = side ? M1 : M0;
    const float* __restrict__ conc = side ? conc1 : conc0;
    const int*   __restrict__ lab  = side ? lab1 : lab0;
    const __nv_bfloat16* __restrict__ Msrc = g_Mb + (size_t)side * CC * DDIM;

    float* __restrict__ ic  = reinterpret_cast<float*>(smem + SM_IC);
    float* __restrict__ red = reinterpret_cast<float*>(smem + SM_RED);
    float* __restrict__ ws  = reinterpret_cast<float*>(smem + SM_WS);
    unsigned int* __restrict__ flg = reinterpret_cast<unsigned int*>(smem + SM_FLAG);

    // ic = log2(e) / conc ; zero reduction buffer
    #pragma unroll
    for (int i = tid; i < CC; i += 256) ic[i] = 1.4426950408889634f / conc[i];
    if (tid < TILE_B) red[tid] = 0.f;

    // F tile: fp32 -> bf16 into swizzled smem (row*256B, unit^(row&7))
    {
        const float* Fp = F + (size_t)bx * TILE_B * DDIM;
        #pragma unroll
        for (int j = 0; j < 8; j++) {
            int u   = tid + j * 256;            // 0..2047 16B units
            int row = u >> 4, un = u & 15;
            const float4* p = reinterpret_cast<const float4*>(Fp + row * DDIM + un * 8);
            float4 a = p[0], b = p[1];
            __nv_bfloat16 t[8] = {
                __float2bfloat16_rn(a.x), __float2bfloat16_rn(a.y),
                __float2bfloat16_rn(a.z), __float2bfloat16_rn(a.w),
                __float2bfloat16_rn(b.x), __float2bfloat16_rn(b.y),
                __float2bfloat16_rn(b.z), __float2bfloat16_rn(b.w) };
            *reinterpret_cast<uint4*>(smem + SM_F + row * ROWB + ((un ^ (row & 7)) << 4)) =
                *reinterpret_cast<uint4*>(t);
        }
    }

    // prefetch chunk 0
    {
        #pragma unroll
        for (int j = 0; j < 4; j++) {
            int u = tid + j * 256;              // 64 rows x 16 units
            int row = u >> 4, un = u & 15;
            CP_ASYNC16(sb + SM_M0 + row * ROWB + ((un ^ (row & 7)) << 4),
                       Msrc + row * DDIM + un * 8);
        }
        CP_COMMIT();
    }

    // per-thread ldmatrix geometry
    const int j8 = lane & 7, g = lane >> 3;
    const int arow = wm * 32 + ((g & 1) << 3) + j8;     // + mt*16
    const int ap   = g >> 1;
    const int brow = ((g >> 1) << 3) + j8;
    const int bp   = g & 1;
    const uint32_t a_base = sb + SM_F + arow * ROWB;
    const int a_swz = arow & 7;
    const int b_swz = brow & 7;
    const uint32_t b_off0 = (wn * 32 + brow) * ROWB;
    const uint32_t b_off1 = (wn * 32 + 16 + brow) * ROWB;

    __syncthreads();    // F tile visible to all warps

    // hoist A fragments (loop-invariant): 2 mt x 8 ks x 4 regs
    uint32_t afr[2][8][4];
    #pragma unroll
    for (int mt = 0; mt < 2; mt++)
        #pragma unroll
        for (int ks = 0; ks < 8; ks++)
            ldsm_x4(afr[mt][ks][0], afr[mt][ks][1], afr[mt][ks][2], afr[mt][ks][3],
                    a_base + mt * 16 * ROWB + ((((ks << 1) + ap) ^ a_swz) << 4));

    float rsum[4] = {0.f, 0.f, 0.f, 0.f};

    for (int i = 0; i < NCH; i++) {
        const int s = i & 1;
        if (i + 1 < NCH) {
            const __nv_bfloat16* Mc = Msrc + (size_t)(i + 1) * TILE_C * DDIM;
            const uint32_t dst = sb + (s ? SM_M0 : SM_M1);
            #pragma unroll
            for (int j = 0; j < 4; j++) {
                int u = tid + j * 256;
                int row = u >> 4, un = u & 15;
                CP_ASYNC16(dst + row * ROWB + ((un ^ (row & 7)) << 4),
                           Mc + row * DDIM + un * 8);
            }
            CP_COMMIT();
            CP_WAIT1();
        } else {
            CP_WAIT0();
        }
        __syncthreads();

        const uint32_t mb = sb + (s ? SM_M1 : SM_M0);

        float c[2][4][4];
        #pragma unroll
        for (int mt = 0; mt < 2; mt++)
            #pragma unroll
            for (int nt = 0; nt < 4; nt++)
                #pragma unroll
                for (int q = 0; q < 4; q++) c[mt][nt][q] = 0.f;

        #pragma unroll
        for (int ks = 0; ks < 8; ks++) {
            uint32_t b[2][4];
            const uint32_t uo = (((ks << 1) + bp) ^ b_swz) << 4;
            ldsm_x4(b[0][0], b[0][1], b[0][2], b[0][3], mb + b_off0 + uo);
            ldsm_x4(b[1][0], b[1][1], b[1][2], b[1][3], mb + b_off1 + uo);
            #pragma unroll
            for (int mt = 0; mt < 2; mt++) {
                #pragma unroll
                for (int h = 0; h < 2; h++) {
                    mma_bf16(c[mt][h*2+0][0], c[mt][h*2+0][1], c[mt][h*2+0][2], c[mt][h*2+0][3],
                             afr[mt][ks][0], afr[mt][ks][1], afr[mt][ks][2], afr[mt][ks][3],
                             b[h][0], b[h][1]);
                    mma_bf16(c[mt][h*2+1][0], c[mt][h*2+1][1], c[mt][h*2+1][2], c[mt][h*2+1][3],
                             afr[mt][ks][0], afr[mt][ks][1], afr[mt][ks][2], afr[mt][ks][3],
                             b[h][2], b[h][3]);
                }
            }
        }
        __syncthreads();   // stage fully read; next prefetch may overwrite

        // epilogue: exp2(d * ic) accumulated into per-thread row sums
        const int colbase = i * TILE_C + wn * 32 + ((lane & 3) << 1);
        float2 icv[4];
        #pragma unroll
        for (int nt = 0; nt < 4; nt++)
            icv[nt] = *reinterpret_cast<const float2*>(ic + colbase + nt * 8);
        #pragma unroll
        for (int mt = 0; mt < 2; mt++)
            #pragma unroll
            for (int nt = 0; nt < 4; nt++) {
                rsum[mt*2+0] += ex2f(c[mt][nt][0] * icv[nt].x) + ex2f(c[mt][nt][1] * icv[nt].y);
                rsum[mt*2+1] += ex2f(c[mt][nt][2] * icv[nt].x) + ex2f(c[mt][nt][3] * icv[nt].y);
            }
    }

    // reduce row sums: quad shfl, then cross-warp smem atomics (2 warps per row)
    #pragma unroll
    for (int i = 0; i < 4; i++) {
        rsum[i] += __shfl_xor_sync(0xFFFFFFFFu, rsum[i], 1);
        rsum[i] += __shfl_xor_sync(0xFFFFFFFFu, rsum[i], 2);
    }
    if ((lane & 3) == 0) {
        const int r0 = wm * 32 + (lane >> 2);
        atomicAdd(red + r0 + 0,  rsum[0]);   // mt0, rows +0
        atomicAdd(red + r0 + 8,  rsum[1]);   // mt0, rows +8
        atomicAdd(red + r0 + 16, rsum[2]);   // mt1, rows +0
        atomicAdd(red + r0 + 24, rsum[3]);   // mt1, rows +8
    }
    __syncthreads();       // red[] = S per sample, complete

    // ---- fused positive logit + per-CTA partial (exact fp32) ----
    float psum = 0.f;
    const int b0 = bx * TILE_B;
    #pragma unroll 4
    for (int j = 0; j < 16; j++) {
        const int bl  = wid * 16 + j;
        const int bgl = b0 + bl;
        const int l = lab[bgl];
        float4 f = reinterpret_cast<const float4*>(F + (size_t)bgl * DDIM)[lane];
        float4 m = reinterpret_cast<const float4*>(Mf + (size_t)l * DDIM)[lane];
        float d = f.x * m.x + f.y * m.y + f.z * m.z + f.w * m.w;
        #pragma unroll
        for (int o = 16; o > 0; o >>= 1) d += __shfl_xor_sync(0xFFFFFFFFu, d, o);
        if (lane == 0)
            psum += d * ic[l] * LN2F - logf(red[bl]);   // pos/conc - ln S
    }
    if (lane == 0) ws[wid] = psum;
    __syncthreads();

    // ---- per-CTA partial + last-block full reduction (threadfence pattern) ----
    if (tid == 0) {
        float s = 0.f;
        #pragma unroll
        for (int i = 0; i < 8; i++) s += ws[i];
        g_part[side * (BB / TILE_B) + bx] = s;
        __threadfence();
        unsigned int v = atomicAdd(&g_cnt, 1u);
        *flg = (v == NBLK - 1) ? 1u : 0u;
    }
    __syncthreads();

    if (*flg) {
        // last CTA: fixed-order deterministic reduction of all 256 partials
        float* smr = ic;   // reuse (ic no longer needed)
        smr[tid] = *((volatile float*)g_part + tid);
        __syncthreads();
        for (int st = 128; st > 0; st >>= 1) {
            if (tid < st) smr[tid] += smr[tid + st];
            __syncthreads();
        }
        if (tid == 0) {
            int iv = lbp[0];
            float lbv = (iv > 1000000 || iv < -1000000) ? __int_as_float(iv) : (float)iv;
            out[0] = (-lbv) * 0.5f / (float)BB * smr[0];
            g_cnt = 0;                 // reset for next graph replay
        }
    }
}

// ---------------- launch ----------------
extern "C" void kernel_launch(void* const* d_in, const int* in_sizes, int n_in,
                              void* d_out, int out_size)
{
    const float* features       = (const float*)d_in[0];
    const float* features_I     = (const float*)d_in[1];
    const float* M_kmeans       = (const float*)d_in[2];
    const float* M_kmeans_I     = (const float*)d_in[3];
    const float* concentrations = (const float*)d_in[4];
    const float* concentr_I     = (const float*)d_in[5];
    const int*   labels         = (const int*)d_in[6];
    const int*   labels_I       = (const int*)d_in[7];
    const int*   lb             = (n_in > 8) ? (const int*)d_in[8] : nullptr;
    float* out = (float*)d_out;

    convM_kernel<<<(2 * CC * DDIM / 4) / 256, 256>>>(M_kmeans, M_kmeans_I);

    cudaFuncSetAttribute(main_kernel,
                         cudaFuncAttributeMaxDynamicSharedMemorySize, SM_TOT);
    main_kernel<<<dim3(BB / TILE_B, 2), 256, SM_TOT>>>(
        features, features_I, M_kmeans, M_kmeans_I,
        concentrations, concentr_I, labels, labels_I, lb, out);
}

// round 7
// speedup vs baseline: 6.5109x; 1.0286x over previous
#include <cuda_runtime.h>
#include <cuda_fp16.h>
#include <math.h>
#include <stdint.h>

#define BB 16384
#define CC 2048
#define DDIM 128
#define TILE_B 128          // samples per CTA
#define TILE_C 64           // centroids per chunk
#define NCH (CC / TILE_C)   // 32 chunks
#define ROWB 256            // bytes per smem row (128 f16)
#define LN2F 0.6931471805599453f
#define NBLK (2 * (BB / TILE_B))   // 256 CTAs total

// ---------------- scratch ----------------
__device__ __align__(16) __half g_Mb[2 * CC * DDIM];  // f16 M, row-major
__device__ float g_part[NBLK];                        // per-CTA partials
__device__ unsigned int g_cnt;                        // completion counter

// ---------------- smem layout (bytes) ----------------
#define SM_F    0
#define SM_M0   32768
#define SM_M1   49152
#define SM_IC   65536
#define SM_RED  73728
#define SM_WS   74240
#define SM_FLAG 74272
#define SM_TOT  74304

__device__ __forceinline__ uint32_t smem_u32(const void* p) {
    uint32_t a;
    asm("{ .reg .u64 t; cvta.to.shared.u64 t, %1; cvt.u32.u64 %0, t; }" : "=r"(a) : "l"(p));
    return a;
}
__device__ __forceinline__ float ex2f(float x) {
    float y; asm("ex2.approx.f32 %0, %1;" : "=f"(y) : "f"(x)); return y;
}
__device__ __forceinline__ void ldsm_x4(uint32_t& r0, uint32_t& r1, uint32_t& r2,
                                        uint32_t& r3, uint32_t addr) {
    asm volatile("ldmatrix.sync.aligned.m8n8.x4.shared.b16 {%0,%1,%2,%3}, [%4];"
                 : "=r"(r0), "=r"(r1), "=r"(r2), "=r"(r3) : "r"(addr));
}
// f16-accumulate HMMA: D(f16x2 x2) = A(f16) * B(f16) + D
__device__ __forceinline__ void mma_f16acc(uint32_t& d0, uint32_t& d1,
                                           uint32_t a0, uint32_t a1, uint32_t a2, uint32_t a3,
                                           uint32_t b0, uint32_t b1) {
    asm volatile("mma.sync.aligned.m16n8k16.row.col.f16.f16.f16.f16 "
                 "{%0,%1}, {%2,%3,%4,%5}, {%6,%7}, {%0,%1};"
                 : "+r"(d0), "+r"(d1)
                 : "r"(a0), "r"(a1), "r"(a2), "r"(a3), "r"(b0), "r"(b1));
}
#define CP_ASYNC16(dst, src) \
    asm volatile("cp.async.cg.shared.global [%0], [%1], 16;" :: "r"(dst), "l"(src) : "memory")
#define CP_COMMIT() asm volatile("cp.async.commit_group;" ::: "memory")
#define CP_WAIT1()  asm volatile("cp.async.wait_group 1;" ::: "memory")
#define CP_WAIT0()  asm volatile("cp.async.wait_group 0;" ::: "memory")

// ---------------- prep: M fp32 -> f16 row-major ----------------
__global__ __launch_bounds__(256)
void convM_kernel(const float* __restrict__ M0, const float* __restrict__ M1)
{
    int i = (blockIdx.x * 256 + threadIdx.x) * 4;
    const int n = CC * DDIM;
    const float* src = (i < n) ? M0 : M1;
    int off = (i < n) ? i : i - n;
    float4 v = *reinterpret_cast<const float4*>(src + off);
    __half b[4] = { __float2half_rn(v.x), __float2half_rn(v.y),
                    __float2half_rn(v.z), __float2half_rn(v.w) };
    *reinterpret_cast<uint2*>(g_Mb + i) = *reinterpret_cast<uint2*>(b);
}

// ---------------- main: GEMM + exp + row-sum + positive + full reduction ----------------
__global__ __launch_bounds__(256, 2)
void main_kernel(const float* __restrict__ features,
                 const float* __restrict__ features_I,
                 const float* __restrict__ M0,
                 const float* __restrict__ M1,
                 const float* __restrict__ conc0,
                 const float* __restrict__ conc1,
                 const int* __restrict__ lab0,
                 const int* __restrict__ lab1,
                 const int* __restrict__ lbp,
                 float* __restrict__ out)
{
    extern __shared__ __align__(1024) unsigned char smem[];
    const uint32_t sb = smem_u32(smem);
    const int tid  = threadIdx.x;
    const int wid  = tid >> 5;
    const int lane = tid & 31;
    const int wm   = wid >> 1;        // 0..3 : m-offset wm*32
    const int wn   = wid & 1;         // 0..1 : n-offset wn*32
    const int side = blockIdx.y;
    const int bx   = blockIdx.x;

    const float* __restrict__ F    = side ? features : features_I;
    const float* __restrict__ Mf   = side ? M1 : M0;
    const float* __restrict__ conc = side ? conc1 : conc0;
    const int*   __restrict__ lab  = side ? lab1 : lab0;
    const __half* __restrict__ Msrc = g_Mb + (size_t)side * CC * DDIM;

    float* __restrict__ ic  = reinterpret_cast<float*>(smem + SM_IC);
    float* __restrict__ red = reinterpret_cast<float*>(smem + SM_RED);
    float* __restrict__ ws  = reinterpret_cast<float*>(smem + SM_WS);
    unsigned int* __restrict__ flg = reinterpret_cast<unsigned int*>(smem + SM_FLAG);

    // ic = log2(e) / conc ; zero reduction buffer
    #pragma unroll
    for (int i = tid; i < CC; i += 256) ic[i] = 1.4426950408889634f / conc[i];
    if (tid < TILE_B) red[tid] = 0.f;

    // F tile: fp32 -> f16 into swizzled smem (row*256B, unit^(row&7))
    {
        const float* Fp = F + (size_t)bx * TILE_B * DDIM;
        #pragma unroll
        for (int j = 0; j < 8; j++) {
            int u   = tid + j * 256;            // 0..2047 16B units
            int row = u >> 4, un = u & 15;
            const float4* p = reinterpret_cast<const float4*>(Fp + row * DDIM + un * 8);
            float4 a = p[0], b = p[1];
            __half t[8] = {
                __float2half_rn(a.x), __float2half_rn(a.y),
                __float2half_rn(a.z), __float2half_rn(a.w),
                __float2half_rn(b.x), __float2half_rn(b.y),
                __float2half_rn(b.z), __float2half_rn(b.w) };
            *reinterpret_cast<uint4*>(smem + SM_F + row * ROWB + ((un ^ (row & 7)) << 4)) =
                *reinterpret_cast<uint4*>(t);
        }
    }

    // prefetch chunk 0
    {
        #pragma unroll
        for (int j = 0; j < 4; j++) {
            int u = tid + j * 256;              // 64 rows x 16 units
            int row = u >> 4, un = u & 15;
            CP_ASYNC16(sb + SM_M0 + row * ROWB + ((un ^ (row & 7)) << 4),
                       Msrc + row * DDIM + un * 8);
        }
        CP_COMMIT();
    }

    // per-thread ldmatrix geometry
    const int j8 = lane & 7, g = lane >> 3;
    const int arow = wm * 32 + ((g & 1) << 3) + j8;     // + mt*16
    const int ap   = g >> 1;
    const int brow = ((g >> 1) << 3) + j8;
    const int bp   = g & 1;
    const uint32_t a_base = sb + SM_F + arow * ROWB;
    const int a_swz = arow & 7;
    const int b_swz = brow & 7;
    const uint32_t b_off0 = (wn * 32 + brow) * ROWB;
    const uint32_t b_off1 = (wn * 32 + 16 + brow) * ROWB;

    __syncthreads();    // F tile visible to all warps

    // hoist A fragments (loop-invariant): 2 mt x 8 ks x 4 regs
    uint32_t afr[2][8][4];
    #pragma unroll
    for (int mt = 0; mt < 2; mt++)
        #pragma unroll
        for (int ks = 0; ks < 8; ks++)
            ldsm_x4(afr[mt][ks][0], afr[mt][ks][1], afr[mt][ks][2], afr[mt][ks][3],
                    a_base + mt * 16 * ROWB + ((((ks << 1) + ap) ^ a_swz) << 4));

    float rsum[4] = {0.f, 0.f, 0.f, 0.f};

    for (int i = 0; i < NCH; i++) {
        const int s = i & 1;
        if (i + 1 < NCH) {
            const __half* Mc = Msrc + (size_t)(i + 1) * TILE_C * DDIM;
            const uint32_t dst = sb + (s ? SM_M0 : SM_M1);
            #pragma unroll
            for (int j = 0; j < 4; j++) {
                int u = tid + j * 256;
                int row = u >> 4, un = u & 15;
                CP_ASYNC16(dst + row * ROWB + ((un ^ (row & 7)) << 4),
                           Mc + row * DDIM + un * 8);
            }
            CP_COMMIT();
            CP_WAIT1();
        } else {
            CP_WAIT0();
        }
        __syncthreads();

        const uint32_t mb = sb + (s ? SM_M1 : SM_M0);

        // f16 accumulators: [mt][nt] x 2 packed regs (rows r / r+8, cols 2j,2j+1)
        uint32_t c[2][4][2];
        #pragma unroll
        for (int mt = 0; mt < 2; mt++)
            #pragma unroll
            for (int nt = 0; nt < 4; nt++)
                c[mt][nt][0] = c[mt][nt][1] = 0u;

        #pragma unroll
        for (int ks = 0; ks < 8; ks++) {
            uint32_t b[2][4];
            const uint32_t uo = (((ks << 1) + bp) ^ b_swz) << 4;
            ldsm_x4(b[0][0], b[0][1], b[0][2], b[0][3], mb + b_off0 + uo);
            ldsm_x4(b[1][0], b[1][1], b[1][2], b[1][3], mb + b_off1 + uo);
            #pragma unroll
            for (int mt = 0; mt < 2; mt++) {
                #pragma unroll
                for (int h = 0; h < 2; h++) {
                    mma_f16acc(c[mt][h*2+0][0], c[mt][h*2+0][1],
                               afr[mt][ks][0], afr[mt][ks][1], afr[mt][ks][2], afr[mt][ks][3],
                               b[h][0], b[h][1]);
                    mma_f16acc(c[mt][h*2+1][0], c[mt][h*2+1][1],
                               afr[mt][ks][0], afr[mt][ks][1], afr[mt][ks][2], afr[mt][ks][3],
                               b[h][2], b[h][3]);
                }
            }
        }
        __syncthreads();   // stage fully read; next prefetch may overwrite

        // epilogue: unpack f16 pairs, scale, exp2, accumulate
        const int colbase = i * TILE_C + wn * 32 + ((lane & 3) << 1);
        float2 icv[4];
        #pragma unroll
        for (int nt = 0; nt < 4; nt++)
            icv[nt] = *reinterpret_cast<const float2*>(ic + colbase + nt * 8);
        #pragma unroll
        for (int mt = 0; mt < 2; mt++)
            #pragma unroll
            for (int nt = 0; nt < 4; nt++) {
                float2 v0 = __half22float2(*reinterpret_cast<__half2*>(&c[mt][nt][0]));
                float2 v1 = __half22float2(*reinterpret_cast<__half2*>(&c[mt][nt][1]));
                rsum[mt*2+0] += ex2f(v0.x * icv[nt].x) + ex2f(v0.y * icv[nt].y);
                rsum[mt*2+1] += ex2f(v1.x * icv[nt].x) + ex2f(v1.y * icv[nt].y);
            }
    }

    // reduce row sums: quad shfl, then cross-warp smem atomics (2 warps per row)
    #pragma unroll
    for (int i = 0; i < 4; i++) {
        rsum[i] += __shfl_xor_sync(0xFFFFFFFFu, rsum[i], 1);
        rsum[i] += __shfl_xor_sync(0xFFFFFFFFu, rsum[i], 2);
    }
    if ((lane & 3) == 0) {
        const int r0 = wm * 32 + (lane >> 2);
        atomicAdd(red + r0 + 0,  rsum[0]);
        atomicAdd(red + r0 + 8,  rsum[1]);
        atomicAdd(red + r0 + 16, rsum[2]);
        atomicAdd(red + r0 + 24, rsum[3]);
    }
    __syncthreads();       // red[] = S per sample, complete

    // ---- fused positive logit + per-CTA partial (exact fp32) ----
    float psum = 0.f;
    const int b0 = bx * TILE_B;
    #pragma unroll 4
    for (int j = 0; j < 16; j++) {
        const int bl  = wid * 16 + j;
        const int bgl = b0 + bl;
        const int l = lab[bgl];
        float4 f = reinterpret_cast<const float4*>(F + (size_t)bgl * DDIM)[lane];
        float4 m = reinterpret_cast<const float4*>(Mf + (size_t)l * DDIM)[lane];
        float d = f.x * m.x + f.y * m.y + f.z * m.z + f.w * m.w;
        #pragma unroll
        for (int o = 16; o > 0; o >>= 1) d += __shfl_xor_sync(0xFFFFFFFFu, d, o);
        if (lane == 0)
            psum += d * ic[l] * LN2F - logf(red[bl]);   // pos/conc - ln S
    }
    if (lane == 0) ws[wid] = psum;
    __syncthreads();

    // ---- per-CTA partial + last-block full reduction (threadfence pattern) ----
    if (tid == 0) {
        float s = 0.f;
        #pragma unroll
        for (int i = 0; i < 8; i++) s += ws[i];
        g_part[side * (BB / TILE_B) + bx] = s;
        __threadfence();
        unsigned int v = atomicAdd(&g_cnt, 1u);
        *flg = (v == NBLK - 1) ? 1u : 0u;
    }
    __syncthreads();

    if (*flg) {
        float* smr = ic;   // reuse
        smr[tid] = *((volatile float*)g_part + tid);
        __syncthreads();
        for (int st = 128; st > 0; st >>= 1) {
            if (tid < st) smr[tid] += smr[tid + st];
            __syncthreads();
        }
        if (tid == 0) {
            int iv = lbp[0];
            float lbv = (iv > 1000000 || iv < -1000000) ? __int_as_float(iv) : (float)iv;
            out[0] = (-lbv) * 0.5f / (float)BB * smr[0];
            g_cnt = 0;                 // reset for next graph replay
        }
    }
}

// ---------------- launch ----------------
extern "C" void kernel_launch(void* const* d_in, const int* in_sizes, int n_in,
                              void* d_out, int out_size)
{
    const float* features       = (const float*)d_in[0];
    const float* features_I     = (const float*)d_in[1];
    const float* M_kmeans       = (const float*)d_in[2];
    const float* M_kmeans_I     = (const float*)d_in[3];
    const float* concentrations = (const float*)d_in[4];
    const float* concentr_I     = (const float*)d_in[5];
    const int*   labels         = (const int*)d_in[6];
    const int*   labels_I       = (const int*)d_in[7];
    const int*   lb             = (n_in > 8) ? (const int*)d_in[8] : nullptr;
    float* out = (float*)d_out;

    convM_kernel<<<(2 * CC * DDIM / 4) / 256, 256>>>(M_kmeans, M_kmeans_I);

    cudaFuncSetAttribute(main_kernel,
                         cudaFuncAttributeMaxDynamicSharedMemorySize, SM_TOT);
    main_kernel<<<dim3(BB / TILE_B, 2), 256, SM_TOT>>>(
        features, features_I, M_kmeans, M_kmeans_I,
        concentrations, concentr_I, labels, labels_I, lb, out);
}

// round 9
// speedup vs baseline: 8.4390x; 1.2961x over previous
#include <cuda_runtime.h>
#include <math.h>
#include <stdint.h>

#define BB 16384
#define CC 2048
#define DDIM 128
#define TILE_B 128          // samples per CTA
#define TILE_C 64           // centroids per chunk
#define NCH (CC / TILE_C)   // 32 chunks
#define ROWB 128            // bytes per smem row (128 int8)
#define LN2F 0.6931471805599453f
#define INVQ 6.2000124e-5f  // 1/(127*127)
#define NBLK (2 * (BB / TILE_B))   // 256 CTAs total

// ---------------- scratch ----------------
__device__ __align__(16) signed char g_Mb[2 * CC * DDIM];  // s8 M, row-major
__device__ float g_part[NBLK];
__device__ unsigned int g_cnt;

// ---------------- smem layout (bytes) ----------------
#define SM_F    0
#define SM_M0   16384
#define SM_M1   24576
#define SM_IC   32768
#define SM_RED  40960
#define SM_WS   41472
#define SM_FLAG 41504
#define SM_TOT  41536

__device__ __forceinline__ uint32_t smem_u32(const void* p) {
    uint32_t a;
    asm("{ .reg .u64 t; cvta.to.shared.u64 t, %1; cvt.u32.u64 %0, t; }" : "=r"(a) : "l"(p));
    return a;
}
__device__ __forceinline__ float ex2f(float x) {
    float y; asm("ex2.approx.f32 %0, %1;" : "=f"(y) : "f"(x)); return y;
}
__device__ __forceinline__ void ldsm_x4(uint32_t& r0, uint32_t& r1, uint32_t& r2,
                                        uint32_t& r3, uint32_t addr) {
    asm volatile("ldmatrix.sync.aligned.m8n8.x4.shared.b16 {%0,%1,%2,%3}, [%4];"
                 : "=r"(r0), "=r"(r1), "=r"(r2), "=r"(r3) : "r"(addr));
}
// s8 MMA: m16n8k32, s32 accumulate
__device__ __forceinline__ void mma_s8(int& c0, int& c1, int& c2, int& c3,
                                       uint32_t a0, uint32_t a1, uint32_t a2, uint32_t a3,
                                       uint32_t b0, uint32_t b1) {
    asm volatile("mma.sync.aligned.m16n8k32.row.col.s32.s8.s8.s32 "
                 "{%0,%1,%2,%3}, {%4,%5,%6,%7}, {%8,%9}, {%0,%1,%2,%3};"
                 : "+r"(c0), "+r"(c1), "+r"(c2), "+r"(c3)
                 : "r"(a0), "r"(a1), "r"(a2), "r"(a3), "r"(b0), "r"(b1));
}
#define CP_ASYNC16(dst, src) \
    asm volatile("cp.async.cg.shared.global [%0], [%1], 16;" :: "r"(dst), "l"(src) : "memory")
#define CP_COMMIT() asm volatile("cp.async.commit_group;" ::: "memory")
#define CP_WAIT1()  asm volatile("cp.async.wait_group 1;" ::: "memory")
#define CP_WAIT0()  asm volatile("cp.async.wait_group 0;" ::: "memory")

// pack 4 floats -> 4 s8 (rn, x127)
__device__ __forceinline__ uint32_t pack_s8x4(float4 v) {
    int a = __float2int_rn(v.x * 127.f), b = __float2int_rn(v.y * 127.f);
    int c = __float2int_rn(v.z * 127.f), d = __float2int_rn(v.w * 127.f);
    return (a & 255) | ((b & 255) << 8) | ((c & 255) << 16) | ((d & 255) << 24);
}

// ---------------- prep: M fp32 -> s8 row-major ----------------
__global__ __launch_bounds__(256)
void convM_kernel(const float* __restrict__ M0, const float* __restrict__ M1)
{
    int i = (blockIdx.x * 256 + threadIdx.x) * 8;      // 8 elements per thread
    const int n = CC * DDIM;
    const float* src = (i < n) ? M0 : M1;
    int off = (i < n) ? i : i - n;
    float4 a = *reinterpret_cast<const float4*>(src + off);
    float4 b = *reinterpret_cast<const float4*>(src + off + 4);
    uint2 w; w.x = pack_s8x4(a); w.y = pack_s8x4(b);
    *reinterpret_cast<uint2*>(g_Mb + i) = w;
}

// ---------------- main: s8 GEMM + exp + row-sum + positive + full reduction ----------------
__global__ __launch_bounds__(256, 2)
void main_kernel(const float* __restrict__ features,
                 const float* __restrict__ features_I,
                 const float* __restrict__ M0,
                 const float* __restrict__ M1,
                 const float* __restrict__ conc0,
                 const float* __restrict__ conc1,
                 const int* __restrict__ lab0,
                 const int* __restrict__ lab1,
                 const int* __restrict__ lbp,
                 float* __restrict__ out)
{
    extern __shared__ __align__(1024) unsigned char smem[];
    const uint32_t sb = smem_u32(smem);
    const int tid  = threadIdx.x;
    const int wid  = tid >> 5;
    const int lane = tid & 31;
    const int wm   = wid >> 1;        // 0..3 : m-offset wm*32
    const int wn   = wid & 1;         // 0..1 : n-offset wn*32
    const int side = blockIdx.y;
    const int bx   = blockIdx.x;

    const float* __restrict__ F    = side ? features : features_I;
    const float* __restrict__ Mf   = side ? M1 : M0;
    const float* __restrict__ conc = side ? conc1 : conc0;
    const int*   __restrict__ lab  = side ? lab1 : lab0;
    const signed char* __restrict__ Msrc = g_Mb + (size_t)side * CC * DDIM;

    float* __restrict__ ic  = reinterpret_cast<float*>(smem + SM_IC);
    float* __restrict__ red = reinterpret_cast<float*>(smem + SM_RED);
    float* __restrict__ ws  = reinterpret_cast<float*>(smem + SM_WS);
    unsigned int* __restrict__ flg = reinterpret_cast<unsigned int*>(smem + SM_FLAG);

    // ic = log2(e)/conc ; zero reduction buffer
    #pragma unroll
    for (int i = tid; i < CC; i += 256) ic[i] = 1.4426950408889634f / conc[i];
    if (tid < TILE_B) red[tid] = 0.f;

    // F tile: fp32 -> s8 into swizzled smem (row*128B, 16B unit ^ (row&7))
    {
        const float* Fp = F + (size_t)bx * TILE_B * DDIM;
        #pragma unroll
        for (int j = 0; j < 4; j++) {
            int u   = tid + j * 256;            // 0..1023 16B units
            int row = u >> 3, un = u & 7;       // 8 units per row
            const float4* p = reinterpret_cast<const float4*>(Fp + row * DDIM + un * 16);
            uint4 w;
            w.x = pack_s8x4(p[0]); w.y = pack_s8x4(p[1]);
            w.z = pack_s8x4(p[2]); w.w = pack_s8x4(p[3]);
            *reinterpret_cast<uint4*>(smem + SM_F + row * ROWB + ((un ^ (row & 7)) << 4)) = w;
        }
    }

    // prefetch chunk 0 (8KB -> 2 units per thread)
    {
        #pragma unroll
        for (int j = 0; j < 2; j++) {
            int u = tid + j * 256;              // 64 rows x 8 units
            int row = u >> 3, un = u & 7;
            CP_ASYNC16(sb + SM_M0 + row * ROWB + ((un ^ (row & 7)) << 4),
                       Msrc + row * DDIM + un * 16);
        }
        CP_COMMIT();
    }

    // per-thread ldmatrix geometry (16B units span k16)
    const int j8 = lane & 7, g = lane >> 3;
    const int arow = wm * 32 + ((g & 1) << 3) + j8;     // + mt*16
    const int ap   = g >> 1;                            // unit parity (k-half of k32)
    const int brow = ((g >> 1) << 3) + j8;
    const int bp   = g & 1;
    const uint32_t a_base = sb + SM_F + arow * ROWB;
    const int a_swz = arow & 7;
    const int b_swz = brow & 7;
    const uint32_t b_off0 = (wn * 32 + brow) * ROWB;
    const uint32_t b_off1 = (wn * 32 + 16 + brow) * ROWB;

    __syncthreads();    // F tile visible

    // hoist A fragments: 2 mt x 4 k32-slices x 4 regs
    uint32_t afr[2][4][4];
    #pragma unroll
    for (int mt = 0; mt < 2; mt++)
        #pragma unroll
        for (int ks = 0; ks < 4; ks++)
            ldsm_x4(afr[mt][ks][0], afr[mt][ks][1], afr[mt][ks][2], afr[mt][ks][3],
                    a_base + mt * 16 * ROWB + ((((ks << 1) + ap) ^ a_swz) << 4));

    float rsum[4] = {0.f, 0.f, 0.f, 0.f};

    for (int i = 0; i < NCH; i++) {
        const int s = i & 1;
        if (i + 1 < NCH) {
            const signed char* Mc = Msrc + (size_t)(i + 1) * TILE_C * DDIM;
            const uint32_t dst = sb + (s ? SM_M0 : SM_M1);
            #pragma unroll
            for (int j = 0; j < 2; j++) {
                int u = tid + j * 256;
                int row = u >> 3, un = u & 7;
                CP_ASYNC16(dst + row * ROWB + ((un ^ (row & 7)) << 4),
                           Mc + row * DDIM + un * 16);
            }
            CP_COMMIT();
            CP_WAIT1();
        } else {
            CP_WAIT0();
        }
        __syncthreads();

        const uint32_t mb = sb + (s ? SM_M1 : SM_M0);

        int c[2][4][4];
        #pragma unroll
        for (int mt = 0; mt < 2; mt++)
            #pragma unroll
            for (int nt = 0; nt < 4; nt++)
                #pragma unroll
                for (int q = 0; q < 4; q++) c[mt][nt][q] = 0;

        #pragma unroll
        for (int ks = 0; ks < 4; ks++) {
            uint32_t b[2][4];
            const uint32_t uo = (((ks << 1) + bp) ^ b_swz) << 4;
            ldsm_x4(b[0][0], b[0][1], b[0][2], b[0][3], mb + b_off0 + uo);
            ldsm_x4(b[1][0], b[1][1], b[1][2], b[1][3], mb + b_off1 + uo);
            // b[h][0],b[h][1] = cols lo8 (k0-15, k16-31); b[h][2],b[h][3] = cols hi8
            #pragma unroll
            for (int mt = 0; mt < 2; mt++) {
                #pragma unroll
                for (int h = 0; h < 2; h++) {
                    mma_s8(c[mt][h*2+0][0], c[mt][h*2+0][1], c[mt][h*2+0][2], c[mt][h*2+0][3],
                           afr[mt][ks][0], afr[mt][ks][1], afr[mt][ks][2], afr[mt][ks][3],
                           b[h][0], b[h][1]);
                    mma_s8(c[mt][h*2+1][0], c[mt][h*2+1][1], c[mt][h*2+1][2], c[mt][h*2+1][3],
                           afr[mt][ks][0], afr[mt][ks][1], afr[mt][ks][2], afr[mt][ks][3],
                           b[h][2], b[h][3]);
                }
            }
        }
        __syncthreads();   // stage fully read

        // epilogue: (float)s32 * (ic*INVQ) -> exp2 -> accumulate
        const int colbase = i * TILE_C + wn * 32 + ((lane & 3) << 1);
        float2 icv[4];
        #pragma unroll
        for (int nt = 0; nt < 4; nt++) {
            icv[nt] = *reinterpret_cast<const float2*>(ic + colbase + nt * 8);
            icv[nt].x *= INVQ; icv[nt].y *= INVQ;
        }
        #pragma unroll
        for (int mt = 0; mt < 2; mt++)
            #pragma unroll
            for (int nt = 0; nt < 4; nt++) {
                rsum[mt*2+0] += ex2f((float)c[mt][nt][0] * icv[nt].x)
                              + ex2f((float)c[mt][nt][1] * icv[nt].y);
                rsum[mt*2+1] += ex2f((float)c[mt][nt][2] * icv[nt].x)
                              + ex2f((float)c[mt][nt][3] * icv[nt].y);
            }
    }

    // reduce row sums: quad shfl, then cross-warp smem atomics
    #pragma unroll
    for (int i = 0; i < 4; i++) {
        rsum[i] += __shfl_xor_sync(0xFFFFFFFFu, rsum[i], 1);
        rsum[i] += __shfl_xor_sync(0xFFFFFFFFu, rsum[i], 2);
    }
    if ((lane & 3) == 0) {
        const int r0 = wm * 32 + (lane >> 2);
        atomicAdd(red + r0 + 0,  rsum[0]);
        atomicAdd(red + r0 + 8,  rsum[1]);
        atomicAdd(red + r0 + 16, rsum[2]);
        atomicAdd(red + r0 + 24, rsum[3]);
    }
    __syncthreads();       // red[] = S per sample

    // ---- fused positive logit + per-CTA partial (exact fp32) ----
    float psum = 0.f;
    const int b0 = bx * TILE_B;
    #pragma unroll 4
    for (int j = 0; j < 16; j++) {
        const int bl  = wid * 16 + j;
        const int bgl = b0 + bl;
        const int l = lab[bgl];
        float4 f = reinterpret_cast<const float4*>(F + (size_t)bgl * DDIM)[lane];
        float4 m = reinterpret_cast<const float4*>(Mf + (size_t)l * DDIM)[lane];
        float d = f.x * m.x + f.y * m.y + f.z * m.z + f.w * m.w;
        #pragma unroll
        for (int o = 16; o > 0; o >>= 1) d += __shfl_xor_sync(0xFFFFFFFFu, d, o);
        if (lane == 0)
            psum += d * ic[l] * LN2F - logf(red[bl]);   // pos/conc - ln S
    }
    if (lane == 0) ws[wid] = psum;
    __syncthreads();

    // ---- per-CTA partial + last-block full reduction ----
    if (tid == 0) {
        float s = 0.f;
        #pragma unroll
        for (int i = 0; i < 8; i++) s += ws[i];
        g_part[side * (BB / TILE_B) + bx] = s;
        __threadfence();
        unsigned int v = atomicAdd(&g_cnt, 1u);
        *flg = (v == NBLK - 1) ? 1u : 0u;
    }
    __syncthreads();

    if (*flg) {
        float* smr = ic;   // reuse
        smr[tid] = *((volatile float*)g_part + tid);
        __syncthreads();
        for (int st = 128; st > 0; st >>= 1) {
            if (tid < st) smr[tid] += smr[tid + st];
            __syncthreads();
        }
        if (tid == 0) {
            int iv = lbp[0];
            float lbv = (iv > 1000000 || iv < -1000000) ? __int_as_float(iv) : (float)iv;
            out[0] = (-lbv) * 0.5f / (float)BB * smr[0];
            g_cnt = 0;                 // reset for next graph replay
        }
    }
}

// ---------------- launch ----------------
extern "C" void kernel_launch(void* const* d_in, const int* in_sizes, int n_in,
                              void* d_out, int out_size)
{
    const float* features       = (const float*)d_in[0];
    const float* features_I     = (const float*)d_in[1];
    const float* M_kmeans       = (const float*)d_in[2];
    const float* M_kmeans_I     = (const float*)d_in[3];
    const float* concentrations = (const float*)d_in[4];
    const float* concentr_I     = (const float*)d_in[5];
    const int*   labels         = (const int*)d_in[6];
    const int*   labels_I       = (const int*)d_in[7];
    const int*   lb             = (n_in > 8) ? (const int*)d_in[8] : nullptr;
    float* out = (float*)d_out;

    convM_kernel<<<(2 * CC * DDIM / 8) / 256, 256>>>(M_kmeans, M_kmeans_I);

    cudaFuncSetAttribute(main_kernel,
                         cudaFuncAttributeMaxDynamicSharedMemorySize, SM_TOT);
    main_kernel<<<dim3(BB / TILE_B, 2), 256, SM_TOT>>>(
        features, features_I, M_kmeans, M_kmeans_I,
        concentrations, concentr_I, labels, labels_I, lb, out);
}

// round 10
// speedup vs baseline: 8.7007x; 1.0310x over previous
#include <cuda_runtime.h>
#include <math.h>
#include <stdint.h>

#define BB 16384
#define CC 2048
#define DDIM 128
#define TILE_B 128          // samples per CTA
#define TILE_C 64           // centroids per chunk
#define NCH (CC / TILE_C)   // 32 chunks
#define ROWB 128            // bytes per smem row (128 int8)
#define LN2F 0.6931471805599453f
#define INVQ 6.2000124e-5f  // 1/(127*127)
#define MAGICI 0x4B400000   // bits of 12582912.0f
#define MAGICF 12582912.0f
#define NBLK (2 * (BB / TILE_B))   // 256 CTAs total

// ---------------- scratch ----------------
__device__ __align__(16) signed char g_Mb[2 * CC * DDIM];  // s8 M, row-major
__device__ float g_part[NBLK];
__device__ unsigned int g_cnt;

// ---------------- smem layout (bytes) ----------------
#define SM_F    0
#define SM_M0   16384
#define SM_M1   24576
#define SM_IC   32768
#define SM_RED  40960
#define SM_WS   41472
#define SM_FLAG 41504
#define SM_TOT  41536

__device__ __forceinline__ uint32_t smem_u32(const void* p) {
    uint32_t a;
    asm("{ .reg .u64 t; cvta.to.shared.u64 t, %1; cvt.u32.u64 %0, t; }" : "=r"(a) : "l"(p));
    return a;
}
__device__ __forceinline__ float ex2f(float x) {
    float y; asm("ex2.approx.f32 %0, %1;" : "=f"(y) : "f"(x)); return y;
}
__device__ __forceinline__ void ldsm_x4(uint32_t& r0, uint32_t& r1, uint32_t& r2,
                                        uint32_t& r3, uint32_t addr) {
    asm volatile("ldmatrix.sync.aligned.m8n8.x4.shared.b16 {%0,%1,%2,%3}, [%4];"
                 : "=r"(r0), "=r"(r1), "=r"(r2), "=r"(r3) : "r"(addr));
}
// s8 MMA: m16n8k32, s32 accumulate
__device__ __forceinline__ void mma_s8(int& c0, int& c1, int& c2, int& c3,
                                       uint32_t a0, uint32_t a1, uint32_t a2, uint32_t a3,
                                       uint32_t b0, uint32_t b1) {
    asm volatile("mma.sync.aligned.m16n8k32.row.col.s32.s8.s8.s32 "
                 "{%0,%1,%2,%3}, {%4,%5,%6,%7}, {%8,%9}, {%0,%1,%2,%3};"
                 : "+r"(c0), "+r"(c1), "+r"(c2), "+r"(c3)
                 : "r"(a0), "r"(a1), "r"(a2), "r"(a3), "r"(b0), "r"(b1));
}
#define CP_ASYNC16(dst, src) \
    asm volatile("cp.async.cg.shared.global [%0], [%1], 16;" :: "r"(dst), "l"(src) : "memory")
#define CP_COMMIT() asm volatile("cp.async.commit_group;" ::: "memory")
#define CP_WAIT1()  asm volatile("cp.async.wait_group 1;" ::: "memory")
#define CP_WAIT0()  asm volatile("cp.async.wait_group 0;" ::: "memory")

// pack 4 floats -> 4 s8 (rn, x127)
__device__ __forceinline__ uint32_t pack_s8x4(float4 v) {
    int a = __float2int_rn(v.x * 127.f), b = __float2int_rn(v.y * 127.f);
    int c = __float2int_rn(v.z * 127.f), d = __float2int_rn(v.w * 127.f);
    return (a & 255) | ((b & 255) << 8) | ((c & 255) << 16) | ((d & 255) << 24);
}

// ---------------- prep: M fp32 -> s8 row-major (16 elem/thread, MLP 4) ----------------
__global__ __launch_bounds__(256)
void convM_kernel(const float* __restrict__ M0, const float* __restrict__ M1)
{
    int i = (blockIdx.x * 256 + threadIdx.x) * 16;
    const int n = CC * DDIM;
    const float* src = (i < n) ? M0 : M1;
    int off = (i < n) ? i : i - n;
    float4 a = *reinterpret_cast<const float4*>(src + off);
    float4 b = *reinterpret_cast<const float4*>(src + off + 4);
    float4 c = *reinterpret_cast<const float4*>(src + off + 8);
    float4 d = *reinterpret_cast<const float4*>(src + off + 12);
    uint4 w;
    w.x = pack_s8x4(a); w.y = pack_s8x4(b);
    w.z = pack_s8x4(c); w.w = pack_s8x4(d);
    *reinterpret_cast<uint4*>(g_Mb + i) = w;
}

// ---------------- main: s8 GEMM + exp + row-sum + positive + full reduction ----------------
__global__ __launch_bounds__(256, 2)
void main_kernel(const float* __restrict__ features,
                 const float* __restrict__ features_I,
                 const float* __restrict__ M0,
                 const float* __restrict__ M1,
                 const float* __restrict__ conc0,
                 const float* __restrict__ conc1,
                 const int* __restrict__ lab0,
                 const int* __restrict__ lab1,
                 const int* __restrict__ lbp,
                 float* __restrict__ out)
{
    extern __shared__ __align__(1024) unsigned char smem[];
    const uint32_t sb = smem_u32(smem);
    const int tid  = threadIdx.x;
    const int wid  = tid >> 5;
    const int lane = tid & 31;
    const int wm   = wid >> 1;        // 0..3 : m-offset wm*32
    const int wn   = wid & 1;         // 0..1 : n-offset wn*32
    const int side = blockIdx.y;
    const int bx   = blockIdx.x;

    const float* __restrict__ F    = side ? features : features_I;
    const float* __restrict__ Mf   = side ? M1 : M0;
    const float* __restrict__ conc = side ? conc1 : conc0;
    const int*   __restrict__ lab  = side ? lab1 : lab0;
    const signed char* __restrict__ Msrc = g_Mb + (size_t)side * CC * DDIM;

    float* __restrict__ ic  = reinterpret_cast<float*>(smem + SM_IC);
    float* __restrict__ red = reinterpret_cast<float*>(smem + SM_RED);
    float* __restrict__ ws  = reinterpret_cast<float*>(smem + SM_WS);
    unsigned int* __restrict__ flg = reinterpret_cast<unsigned int*>(smem + SM_FLAG);

    // ic = log2(e)/conc ; zero reduction buffer
    #pragma unroll
    for (int i = tid; i < CC; i += 256) ic[i] = 1.4426950408889634f / conc[i];
    if (tid < TILE_B) red[tid] = 0.f;

    // F tile: fp32 -> s8 into swizzled smem (row*128B, 16B unit ^ (row&7))
    {
        const float* Fp = F + (size_t)bx * TILE_B * DDIM;
        #pragma unroll
        for (int j = 0; j < 4; j++) {
            int u   = tid + j * 256;            // 0..1023 16B units
            int row = u >> 3, un = u & 7;       // 8 units per row
            const float4* p = reinterpret_cast<const float4*>(Fp + row * DDIM + un * 16);
            uint4 w;
            w.x = pack_s8x4(p[0]); w.y = pack_s8x4(p[1]);
            w.z = pack_s8x4(p[2]); w.w = pack_s8x4(p[3]);
            *reinterpret_cast<uint4*>(smem + SM_F + row * ROWB + ((un ^ (row & 7)) << 4)) = w;
        }
    }

    // prefetch chunk 0 (8KB -> 2 units per thread)
    {
        #pragma unroll
        for (int j = 0; j < 2; j++) {
            int u = tid + j * 256;              // 64 rows x 8 units
            int row = u >> 3, un = u & 7;
            CP_ASYNC16(sb + SM_M0 + row * ROWB + ((un ^ (row & 7)) << 4),
                       Msrc + row * DDIM + un * 16);
        }
        CP_COMMIT();
    }

    // per-thread ldmatrix geometry (16B units span k16)
    const int j8 = lane & 7, g = lane >> 3;
    const int arow = wm * 32 + ((g & 1) << 3) + j8;     // + mt*16
    const int ap   = g >> 1;                            // unit parity (k-half of k32)
    const int brow = ((g >> 1) << 3) + j8;
    const int bp   = g & 1;
    const uint32_t a_base = sb + SM_F + arow * ROWB;
    const int a_swz = arow & 7;
    const int b_swz = brow & 7;
    const uint32_t b_off0 = (wn * 32 + brow) * ROWB;
    const uint32_t b_off1 = (wn * 32 + 16 + brow) * ROWB;

    __syncthreads();    // F tile visible

    // hoist A fragments: 2 mt x 4 k32-slices x 4 regs
    uint32_t afr[2][4][4];
    #pragma unroll
    for (int mt = 0; mt < 2; mt++)
        #pragma unroll
        for (int ks = 0; ks < 4; ks++)
            ldsm_x4(afr[mt][ks][0], afr[mt][ks][1], afr[mt][ks][2], afr[mt][ks][3],
                    a_base + mt * 16 * ROWB + ((((ks << 1) + ap) ^ a_swz) << 4));

    float rsum[4] = {0.f, 0.f, 0.f, 0.f};

    for (int i = 0; i < NCH; i++) {
        const int s = i & 1;
        if (i + 1 < NCH) {
            const signed char* Mc = Msrc + (size_t)(i + 1) * TILE_C * DDIM;
            const uint32_t dst = sb + (s ? SM_M0 : SM_M1);
            #pragma unroll
            for (int j = 0; j < 2; j++) {
                int u = tid + j * 256;
                int row = u >> 3, un = u & 7;
                CP_ASYNC16(dst + row * ROWB + ((un ^ (row & 7)) << 4),
                           Mc + row * DDIM + un * 16);
            }
            CP_COMMIT();
            CP_WAIT1();
        } else {
            CP_WAIT0();
        }
        __syncthreads();

        const uint32_t mb = sb + (s ? SM_M1 : SM_M0);

        // accumulators pre-biased with MAGICI: after MMA, bits-as-float = MAGICF + dot
        int c[2][4][4];
        #pragma unroll
        for (int mt = 0; mt < 2; mt++)
            #pragma unroll
            for (int nt = 0; nt < 4; nt++)
                #pragma unroll
                for (int q = 0; q < 4; q++) c[mt][nt][q] = MAGICI;

        #pragma unroll
        for (int ks = 0; ks < 4; ks++) {
            uint32_t b[2][4];
            const uint32_t uo = (((ks << 1) + bp) ^ b_swz) << 4;
            ldsm_x4(b[0][0], b[0][1], b[0][2], b[0][3], mb + b_off0 + uo);
            ldsm_x4(b[1][0], b[1][1], b[1][2], b[1][3], mb + b_off1 + uo);
            #pragma unroll
            for (int mt = 0; mt < 2; mt++) {
                #pragma unroll
                for (int h = 0; h < 2; h++) {
                    mma_s8(c[mt][h*2+0][0], c[mt][h*2+0][1], c[mt][h*2+0][2], c[mt][h*2+0][3],
                           afr[mt][ks][0], afr[mt][ks][1], afr[mt][ks][2], afr[mt][ks][3],
                           b[h][0], b[h][1]);
                    mma_s8(c[mt][h*2+1][0], c[mt][h*2+1][1], c[mt][h*2+1][2], c[mt][h*2+1][3],
                           afr[mt][ks][0], afr[mt][ks][1], afr[mt][ks][2], afr[mt][ks][3],
                           b[h][2], b[h][3]);
                }
            }
        }
        __syncthreads();   // stage fully read

        // epilogue: ex2( bits_as_float * s + bias ), bias = -MAGICF*s  (no I2F!)
        const int colbase = i * TILE_C + wn * 32 + ((lane & 3) << 1);
        float2 sv[4], bv[4];
        #pragma unroll
        for (int nt = 0; nt < 4; nt++) {
            float2 v = *reinterpret_cast<const float2*>(ic + colbase + nt * 8);
            sv[nt].x = v.x * INVQ;          sv[nt].y = v.y * INVQ;
            bv[nt].x = -MAGICF * sv[nt].x;  bv[nt].y = -MAGICF * sv[nt].y;
        }
        #pragma unroll
        for (int mt = 0; mt < 2; mt++)
            #pragma unroll
            for (int nt = 0; nt < 4; nt++) {
                rsum[mt*2+0] += ex2f(fmaf(__int_as_float(c[mt][nt][0]), sv[nt].x, bv[nt].x))
                              + ex2f(fmaf(__int_as_float(c[mt][nt][1]), sv[nt].y, bv[nt].y));
                rsum[mt*2+1] += ex2f(fmaf(__int_as_float(c[mt][nt][2]), sv[nt].x, bv[nt].x))
                              + ex2f(fmaf(__int_as_float(c[mt][nt][3]), sv[nt].y, bv[nt].y));
            }
    }

    // reduce row sums: quad shfl, then cross-warp smem atomics
    #pragma unroll
    for (int i = 0; i < 4; i++) {
        rsum[i] += __shfl_xor_sync(0xFFFFFFFFu, rsum[i], 1);
        rsum[i] += __shfl_xor_sync(0xFFFFFFFFu, rsum[i], 2);
    }
    if ((lane & 3) == 0) {
        const int r0 = wm * 32 + (lane >> 2);
        atomicAdd(red + r0 + 0,  rsum[0]);
        atomicAdd(red + r0 + 8,  rsum[1]);
        atomicAdd(red + r0 + 16, rsum[2]);
        atomicAdd(red + r0 + 24, rsum[3]);
    }
    __syncthreads();       // red[] = S per sample

    // ---- fused positive logit + per-CTA partial (exact fp32) ----
    float psum = 0.f;
    const int b0 = bx * TILE_B;
    #pragma unroll 4
    for (int j = 0; j < 16; j++) {
        const int bl  = wid * 16 + j;
        const int bgl = b0 + bl;
        const int l = lab[bgl];
        float4 f = reinterpret_cast<const float4*>(F + (size_t)bgl * DDIM)[lane];
        float4 m = reinterpret_cast<const float4*>(Mf + (size_t)l * DDIM)[lane];
        float d = f.x * m.x + f.y * m.y + f.z * m.z + f.w * m.w;
        #pragma unroll
        for (int o = 16; o > 0; o >>= 1) d += __shfl_xor_sync(0xFFFFFFFFu, d, o);
        if (lane == 0)
            psum += d * ic[l] * LN2F - logf(red[bl]);   // pos/conc - ln S
    }
    if (lane == 0) ws[wid] = psum;
    __syncthreads();

    // ---- per-CTA partial + last-block full reduction ----
    if (tid == 0) {
        float s = 0.f;
        #pragma unroll
        for (int i = 0; i < 8; i++) s += ws[i];
        g_part[side * (BB / TILE_B) + bx] = s;
        __threadfence();
        unsigned int v = atomicAdd(&g_cnt, 1u);
        *flg = (v == NBLK - 1) ? 1u : 0u;
    }
    __syncthreads();

    if (*flg) {
        float* smr = ic;   // reuse
        smr[tid] = *((volatile float*)g_part + tid);
        __syncthreads();
        for (int st = 128; st > 0; st >>= 1) {
            if (tid < st) smr[tid] += smr[tid + st];
            __syncthreads();
        }
        if (tid == 0) {
            int iv = lbp[0];
            float lbv = (iv > 1000000 || iv < -1000000) ? __int_as_float(iv) : (float)iv;
            out[0] = (-lbv) * 0.5f / (float)BB * smr[0];
            g_cnt = 0;                 // reset for next graph replay
        }
    }
}

// ---------------- launch ----------------
extern "C" void kernel_launch(void* const* d_in, const int* in_sizes, int n_in,
                              void* d_out, int out_size)
{
    const float* features       = (const float*)d_in[0];
    const float* features_I     = (const float*)d_in[1];
    const float* M_kmeans       = (const float*)d_in[2];
    const float* M_kmeans_I     = (const float*)d_in[3];
    const float* concentrations = (const float*)d_in[4];
    const float* concentr_I     = (const float*)d_in[5];
    const int*   labels         = (const int*)d_in[6];
    const int*   labels_I       = (const int*)d_in[7];
    const int*   lb             = (n_in > 8) ? (const int*)d_in[8] : nullptr;
    float* out = (float*)d_out;

    convM_kernel<<<(2 * CC * DDIM / 16) / 256, 256>>>(M_kmeans, M_kmeans_I);

    cudaFuncSetAttribute(main_kernel,
                         cudaFuncAttributeMaxDynamicSharedMemorySize, SM_TOT);
    main_kernel<<<dim3(BB / TILE_B, 2), 256, SM_TOT>>>(
        features, features_I, M_kmeans, M_kmeans_I,
        concentrations, concentr_I, labels, labels_I, lb, out);
}